// round 8
// baseline (speedup 1.0000x reference)
#include <cuda_runtime.h>
#include <cuda_fp16.h>
#include <cstdint>

// Shapes (fixed)
#define B_      2048
#define OBS_    4096
#define G_      4096
#define I_      16
#define H_      8
#define A_      18
#define F_      36864

#define BM      16
#define THREADS 512
#define GT      64
#define NT2     64

#define QSTRIDE 4100        // uint2 words per quad row (4096 + 4 pad)

// ---- kernel A smem (bytes) ----
#define OBS_OFF   0
#define OBS_BYTES (4 * QSTRIDE * 8)          // 131200
#define WD_BYTES  (GT * 544)                 // 34816
#define IDX_BYTES (GT * 80)                  // 5120
#define BUF_BYTES (WD_BYTES + IDX_BYTES)     // 39936
#define WD0_OFF   (OBS_OFF + OBS_BYTES)
#define IDX0_OFF  (WD0_OFF + WD_BYTES)
#define WD1_OFF   (WD0_OFF + BUF_BYTES)
#define IDX1_OFF  (WD1_OFF + WD_BYTES)
#define SMEMA_BYTES (WD1_OFF + BUF_BYTES)    // 211072

// ---- kernel B (HMMA GEMM) ----
#define KB_KSPL   9
#define KB_KPER   (F_ / KB_KSPL)             // 4096 halfs per split
#define KB_CHUNK  64                         // halfs per chunk (128 B)
#define KB_NCH    (KB_KPER / KB_CHUNK)       // 64 chunks
#define KB_STAGES 4
#define KB_ASZ    (128 * 128)                // 16 KB per A stage
#define SMEMB_BYTES (KB_STAGES * KB_ASZ)     // 65536
#define KT_TOT    (F_ / 16)                  // 2304 k-tiles
#define NTILES    3                          // N = 24 (>=18)

// ---- device scratch ----
__device__ __align__(16) __half g_X[(size_t)B_ * F_];          // 151MB fp16 features
__device__ uint2  g_gvfWl[(size_t)G_ * 64];                    // dup'd fp16 gvf weights
__device__ uint2  g_qfrag[(size_t)KT_TOT * NTILES * 32];       // B in mma frag order

// ================= helpers =================
__device__ __forceinline__ uint32_t smem_u32(const void* p) {
    return (uint32_t)__cvta_generic_to_shared(p);
}
__device__ __forceinline__ __half2 as_h2(unsigned u) { return *reinterpret_cast<__half2*>(&u); }

#define CPA16(dst, src) asm volatile("cp.async.cg.shared.global [%0], [%1], 16;" :: "r"(dst), "l"(src))
#define CPCOMMIT()      asm volatile("cp.async.commit_group;")
#define CPWAIT(n)       asm volatile("cp.async.wait_group %0;" :: "n"(n))

// ================= prep kernels =================
__global__ void prep_obsX(const float* __restrict__ obs) {
    int idx = blockIdx.x * 256 + threadIdx.x;        // B_*OBS_/4 threads
    int row = idx >> 10;                             // OBS_/4 = 1024
    int c4  = (idx & 1023) * 4;
    float4 v = *reinterpret_cast<const float4*>(obs + (size_t)row * OBS_ + c4);
    __half2 a = __floats2half2_rn(v.x, v.y);
    __half2 b = __floats2half2_rn(v.z, v.w);
    uint2 o;
    o.x = *reinterpret_cast<unsigned*>(&a);
    o.y = *reinterpret_cast<unsigned*>(&b);
    *reinterpret_cast<uint2*>(g_X + (size_t)row * F_ + c4) = o;
}

__global__ void prep_gvfWl(const float* __restrict__ gvfW) {
    int e = blockIdx.x * 256 + threadIdx.x;
    if (e >= G_ * 64) return;
    int g = e >> 6, r = e & 63;
    int hh = r >> 5, p = (r >> 2) & 7, hp = r & 3;
    int h = hh * 4 + hp;
    float w0 = gvfW[(size_t)g * 128 + h * 16 + 2 * p];
    float w1 = gvfW[(size_t)g * 128 + h * 16 + 2 * p + 1];
    unsigned u0 = (unsigned)__half_as_ushort(__float2half(w0)); u0 |= u0 << 16;
    unsigned u1 = (unsigned)__half_as_ushort(__float2half(w1)); u1 |= u1 << 16;
    uint2 o; o.x = u0; o.y = u1;
    g_gvfWl[e] = o;
}

// Pack qW into mma.m16n8k16 B-fragment order.
// frag element map (lane l, reg r): n = nt*8 + l/4, k = kt*16 + 2*(l%4) + r*8 + {0,1}
__global__ void prep_qfrag(const float* __restrict__ qW) {
    int e = blockIdx.x * 256 + threadIdx.x;          // KT_TOT*NTILES*32
    if (e >= KT_TOT * NTILES * 32) return;
    int lane = e & 31;
    int nt   = (e >> 5) % NTILES;
    int kt   = e / (32 * NTILES);
    int n = nt * 8 + (lane >> 2);
    int kb = kt * 16 + 2 * (lane & 3);
    uint2 o;
#pragma unroll
    for (int r = 0; r < 2; r++) {
        int k = kb + r * 8;
        float v0 = (n < A_) ? qW[(size_t)n * F_ + k]     : 0.f;
        float v1 = (n < A_) ? qW[(size_t)n * F_ + k + 1] : 0.f;
        unsigned u = (unsigned)__half_as_ushort(__float2half(v0))
                   | ((unsigned)__half_as_ushort(__float2half(v1)) << 16);
        if (r == 0) o.x = u; else o.y = u;
    }
    g_qfrag[e] = o;
}

__global__ void zero_out(float* out) {
    int e = blockIdx.x * 256 + threadIdx.x;
    if (e < B_ * A_) out[e] = 0.f;
}

// ================= kernel A: gather + GVF layer -> g_X =================
__global__ __launch_bounds__(THREADS, 1)
void gvf_kernel(const float* __restrict__ obs,
                const int*   __restrict__ gidx) {
    extern __shared__ char smem[];
    uint2* sObs = reinterpret_cast<uint2*>(smem + OBS_OFF);

    const int t     = threadIdx.x;
    const int bBase = blockIdx.x * BM;

    const uint32_t wdA[2]  = { smem_u32(smem + WD0_OFF),  smem_u32(smem + WD1_OFF) };
    const uint32_t idxA[2] = { smem_u32(smem + IDX0_OFF), smem_u32(smem + IDX1_OFF) };

    // prologue: weight/idx groups for tiles 0,1
#pragma unroll
    for (int pt = 0; pt < 2; pt++) {
        const uint4* srcW = reinterpret_cast<const uint4*>(g_gvfWl) + (size_t)pt * 2048;
#pragma unroll
        for (int j = 0; j < 4; j++) {
            int e = j * THREADS + t;
            int gg = e >> 5, k = e & 31;
            CPA16(wdA[pt] + gg * 544 + k * 16, srcW + e);
        }
        if (t < 256) {
            int gg = t >> 2, j = t & 3;
            CPA16(idxA[pt] + gg * 80 + j * 16, gidx + (size_t)(pt * GT + gg) * 16 + j * 4);
        }
        CPCOMMIT();
    }

    // obs -> smem quads (fp16, 4 batch rows per uint2)
    for (int e = t; e < 4 * (OBS_ / 4); e += THREADS) {
        int q = e >> 10;
        int f = (e & 1023) * 4;
        float4 v0 = *reinterpret_cast<const float4*>(&obs[(size_t)(bBase + 4 * q + 0) * OBS_ + f]);
        float4 v1 = *reinterpret_cast<const float4*>(&obs[(size_t)(bBase + 4 * q + 1) * OBS_ + f]);
        float4 v2 = *reinterpret_cast<const float4*>(&obs[(size_t)(bBase + 4 * q + 2) * OBS_ + f]);
        float4 v3 = *reinterpret_cast<const float4*>(&obs[(size_t)(bBase + 4 * q + 3) * OBS_ + f]);
        uint2* dst = &sObs[q * QSTRIDE + f];
        __half2 a0 = __floats2half2_rn(v0.x, v1.x), b0 = __floats2half2_rn(v2.x, v3.x);
        __half2 a1 = __floats2half2_rn(v0.y, v1.y), b1 = __floats2half2_rn(v2.y, v3.y);
        __half2 a2 = __floats2half2_rn(v0.z, v1.z), b2 = __floats2half2_rn(v2.z, v3.z);
        __half2 a3 = __floats2half2_rn(v0.w, v1.w), b3 = __floats2half2_rn(v2.w, v3.w);
        uint4 s0, s1;
        s0.x = *reinterpret_cast<unsigned*>(&a0); s0.y = *reinterpret_cast<unsigned*>(&b0);
        s0.z = *reinterpret_cast<unsigned*>(&a1); s0.w = *reinterpret_cast<unsigned*>(&b1);
        s1.x = *reinterpret_cast<unsigned*>(&a2); s1.y = *reinterpret_cast<unsigned*>(&b2);
        s1.z = *reinterpret_cast<unsigned*>(&a3); s1.w = *reinterpret_cast<unsigned*>(&b3);
        *reinterpret_cast<uint4*>(dst)     = s0;
        *reinterpret_cast<uint4*>(dst + 2) = s1;
    }

    const int sp = t & 3;
    const int gs = (t >> 2) & 63;
    const int hh = t >> 8;           // 0/1 -> heads 4hh..4hh+3
    const uint2* qrow = sObs + sp * QSTRIDE;
    const __half2 hz = __floats2half2_rn(0.f, 0.f);

    for (int ti = 0; ti < NT2; ti++) {
        const int sel = ti & 1;
        if (ti < NT2 - 1) { CPWAIT(1); } else { CPWAIT(0); }
        __syncthreads();

        const char* wdRow = smem + ((sel == 0) ? WD0_OFF : WD1_OFF) + gs * 544 + hh * 256;
        const int*  ip    = reinterpret_cast<const int*>(
                                smem + ((sel == 0) ? IDX0_OFF : IDX1_OFF)) + gs * 20;

        __half2 f01[4], f23[4];
#pragma unroll
        for (int j = 0; j < 4; j++) { f01[j] = hz; f23[j] = hz; }
#pragma unroll
        for (int c = 0; c < 2; c++) {
            int4 ia = *reinterpret_cast<const int4*>(ip + c * 8);
            int4 ib = *reinterpret_cast<const int4*>(ip + c * 8 + 4);
            int id[8] = { ia.x, ia.y, ia.z, ia.w, ib.x, ib.y, ib.z, ib.w };
#pragma unroll
            for (int pq = 0; pq < 4; pq++) {
                uint2 x0 = qrow[id[2 * pq]];
                uint2 x1 = qrow[id[2 * pq + 1]];
                int p = c * 4 + pq;
                uint4 wA = *reinterpret_cast<const uint4*>(wdRow + p * 32);
                uint4 wB = *reinterpret_cast<const uint4*>(wdRow + p * 32 + 16);
                f01[0] = __hfma2(as_h2(x0.x), as_h2(wA.x), f01[0]);
                f23[0] = __hfma2(as_h2(x0.y), as_h2(wA.x), f23[0]);
                f01[0] = __hfma2(as_h2(x1.x), as_h2(wA.y), f01[0]);
                f23[0] = __hfma2(as_h2(x1.y), as_h2(wA.y), f23[0]);
                f01[1] = __hfma2(as_h2(x0.x), as_h2(wA.z), f01[1]);
                f23[1] = __hfma2(as_h2(x0.y), as_h2(wA.z), f23[1]);
                f01[1] = __hfma2(as_h2(x1.x), as_h2(wA.w), f01[1]);
                f23[1] = __hfma2(as_h2(x1.y), as_h2(wA.w), f23[1]);
                f01[2] = __hfma2(as_h2(x0.x), as_h2(wB.x), f01[2]);
                f23[2] = __hfma2(as_h2(x0.y), as_h2(wB.x), f23[2]);
                f01[2] = __hfma2(as_h2(x1.x), as_h2(wB.y), f01[2]);
                f23[2] = __hfma2(as_h2(x1.y), as_h2(wB.y), f23[2]);
                f01[3] = __hfma2(as_h2(x0.x), as_h2(wB.z), f01[3]);
                f23[3] = __hfma2(as_h2(x0.y), as_h2(wB.z), f23[3]);
                f01[3] = __hfma2(as_h2(x1.x), as_h2(wB.w), f01[3]);
                f23[3] = __hfma2(as_h2(x1.y), as_h2(wB.w), f23[3]);
            }
        }

#pragma unroll
        for (int j = 0; j < 4; j++) { f01[j] = __hmax2(f01[j], hz); f23[j] = __hmax2(f23[j], hz); }
        const size_t gcol = (size_t)OBS_ + (size_t)(ti * GT + gs) * 8 + 4 * hh;
        {
            __half2 p0 = __lows2half2(f01[0], f01[1]);
            __half2 p1 = __lows2half2(f01[2], f01[3]);
            uint2 u; u.x = *reinterpret_cast<unsigned*>(&p0); u.y = *reinterpret_cast<unsigned*>(&p1);
            *reinterpret_cast<uint2*>(g_X + (size_t)(bBase + 4 * sp + 0) * F_ + gcol) = u;
        }
        {
            __half2 p0 = __highs2half2(f01[0], f01[1]);
            __half2 p1 = __highs2half2(f01[2], f01[3]);
            uint2 u; u.x = *reinterpret_cast<unsigned*>(&p0); u.y = *reinterpret_cast<unsigned*>(&p1);
            *reinterpret_cast<uint2*>(g_X + (size_t)(bBase + 4 * sp + 1) * F_ + gcol) = u;
        }
        {
            __half2 p0 = __lows2half2(f23[0], f23[1]);
            __half2 p1 = __lows2half2(f23[2], f23[3]);
            uint2 u; u.x = *reinterpret_cast<unsigned*>(&p0); u.y = *reinterpret_cast<unsigned*>(&p1);
            *reinterpret_cast<uint2*>(g_X + (size_t)(bBase + 4 * sp + 2) * F_ + gcol) = u;
        }
        {
            __half2 p0 = __highs2half2(f23[0], f23[1]);
            __half2 p1 = __highs2half2(f23[2], f23[3]);
            uint2 u; u.x = *reinterpret_cast<unsigned*>(&p0); u.y = *reinterpret_cast<unsigned*>(&p1);
            *reinterpret_cast<uint2*>(g_X + (size_t)(bBase + 4 * sp + 3) * F_ + gcol) = u;
        }

        __syncthreads();
        if (ti + 2 < NT2) {
            const uint4* srcW = reinterpret_cast<const uint4*>(g_gvfWl) + (size_t)(ti + 2) * 2048;
#pragma unroll
            for (int j = 0; j < 4; j++) {
                int e = j * THREADS + t;
                int gg = e >> 5, k = e & 31;
                CPA16(wdA[sel] + gg * 544 + k * 16, srcW + e);
            }
            if (t < 256) {
                int gg = t >> 2, j = t & 3;
                CPA16(idxA[sel] + gg * 80 + j * 16,
                      gidx + (size_t)((ti + 2) * GT + gg) * 16 + j * 4);
            }
            CPCOMMIT();
        }
    }
}

// ================= kernel B: q-GEMM via mma.sync (HMMA) =================
__global__ __launch_bounds__(256, 1)
void qgemm_kernel(float* __restrict__ out) {
    extern __shared__ char smem[];
    const int t    = threadIdx.x;
    const int wid  = t >> 5;        // 8 warps, 16 rows each
    const int lane = t & 31;
    const int mt   = blockIdx.x & 15;
    const int ks   = blockIdx.x >> 4;    // 0..8

    const uint32_t sA = smem_u32(smem);
    const int rowBase = mt * 128;
    const int kBase   = ks * KB_KPER;

    // cp.async A chunk loader: 128 rows x 64 halfs, 128B rows, XOR-16B swizzle
    auto load_chunk = [&](int c) {
        int st = c & (KB_STAGES - 1);
        uint32_t base = sA + st * KB_ASZ;
        int row = t >> 1;
        int hs  = t & 1;
        const __half* src = g_X + (size_t)(rowBase + row) * F_ + kBase + c * KB_CHUNK + hs * 32;
        uint32_t rb = base + row * 128;
        uint32_t sw = (row & 7) << 4;
#pragma unroll
        for (int s = 0; s < 4; s++) {
            uint32_t byte = hs * 64 + s * 16;
            CPA16(rb + (byte ^ sw), src + s * 8);
        }
    };

    float acc[NTILES][4];
#pragma unroll
    for (int nt = 0; nt < NTILES; nt++)
#pragma unroll
        for (int r = 0; r < 4; r++) acc[nt][r] = 0.f;

    // prologue: stages 0..2
#pragma unroll
    for (int c = 0; c < KB_STAGES - 1; c++) { load_chunk(c); CPCOMMIT(); }

    const int warpM = wid * 16;
    const int lrow  = warpM + (lane & 15);
    const uint32_t lsw = ((lrow & 7) << 4);
    const uint32_t lseg = ((lane >> 4) << 4);

    for (int c = 0; c < KB_NCH; c++) {
        __syncthreads();                       // stage (c+3)&3 free
        if (c + KB_STAGES - 1 < KB_NCH) {
            load_chunk(c + KB_STAGES - 1);
            CPCOMMIT();
            CPWAIT(KB_STAGES - 1);
        } else {
            CPWAIT(0);
        }
        __syncthreads();                       // chunk c visible

        uint32_t stBase = sA + (c & (KB_STAGES - 1)) * KB_ASZ + lrow * 128;

        // B fragments for this chunk (4 k-tiles x 3 n-tiles)
        uint2 bf[4][NTILES];
#pragma unroll
        for (int j = 0; j < 4; j++) {
            int gkt = kBase / 16 + c * 4 + j;
#pragma unroll
            for (int nt = 0; nt < NTILES; nt++)
                bf[j][nt] = __ldg(&g_qfrag[((size_t)gkt * NTILES + nt) * 32 + lane]);
        }

#pragma unroll
        for (int j = 0; j < 4; j++) {
            uint32_t a0, a1, a2, a3;
            uint32_t addr = stBase + ((j * 32 + lseg) ^ lsw);
            asm volatile("ldmatrix.sync.aligned.m8n8.x4.shared.b16 {%0,%1,%2,%3}, [%4];"
                         : "=r"(a0), "=r"(a1), "=r"(a2), "=r"(a3) : "r"(addr));
#pragma unroll
            for (int nt = 0; nt < NTILES; nt++) {
                asm volatile(
                    "mma.sync.aligned.m16n8k16.row.col.f32.f16.f16.f32 "
                    "{%0,%1,%2,%3}, {%4,%5,%6,%7}, {%8,%9}, {%0,%1,%2,%3};"
                    : "+f"(acc[nt][0]), "+f"(acc[nt][1]), "+f"(acc[nt][2]), "+f"(acc[nt][3])
                    : "r"(a0), "r"(a1), "r"(a2), "r"(a3),
                      "r"(bf[j][nt].x), "r"(bf[j][nt].y));
            }
        }
    }

    // epilogue: atomicAdd into out (split-K partials)
    const int gid = lane >> 2, tig = lane & 3;
    const int r0 = rowBase + warpM + gid;
    const int r1 = r0 + 8;
#pragma unroll
    for (int nt = 0; nt < NTILES; nt++) {
        int col = nt * 8 + 2 * tig;
        if (col < A_)     atomicAdd(out + (size_t)r0 * A_ + col,     acc[nt][0]);
        if (col + 1 < A_) atomicAdd(out + (size_t)r0 * A_ + col + 1, acc[nt][1]);
        if (col < A_)     atomicAdd(out + (size_t)r1 * A_ + col,     acc[nt][2]);
        if (col + 1 < A_) atomicAdd(out + (size_t)r1 * A_ + col + 1, acc[nt][3]);
    }
}

// ================= launch =================
extern "C" void kernel_launch(void* const* d_in, const int* in_sizes, int n_in,
                              void* d_out, int out_size) {
    const float* obs  = (const float*)d_in[0];
    const float* gvfW = (const float*)d_in[1];
    const float* qW   = (const float*)d_in[2];
    const int*   gidx = (const int*)d_in[3];
    float* out = (float*)d_out;

    prep_obsX<<<(B_ * OBS_ / 4) / 256, 256>>>(obs);
    prep_gvfWl<<<(G_ * 64 + 255) / 256, 256>>>(gvfW);
    prep_qfrag<<<(KT_TOT * NTILES * 32 + 255) / 256, 256>>>(qW);
    zero_out<<<(B_ * A_ + 255) / 256, 256>>>(out);

    cudaFuncSetAttribute(gvf_kernel,
                         cudaFuncAttributeMaxDynamicSharedMemorySize, SMEMA_BYTES);
    gvf_kernel<<<B_ / BM, THREADS, SMEMA_BYTES>>>(obs, gidx);

    cudaFuncSetAttribute(qgemm_kernel,
                         cudaFuncAttributeMaxDynamicSharedMemorySize, SMEMB_BYTES);
    qgemm_kernel<<<16 * KB_KSPL, 256, SMEMB_BYTES>>>(out);
}

// round 9
// speedup vs baseline: 1.4545x; 1.4545x over previous
#include <cuda_runtime.h>
#include <cuda_fp16.h>
#include <cstdint>

// Shapes (fixed)
#define B_      2048
#define OBS_    4096
#define G_      4096
#define I_      16
#define H_      8
#define A_      18
#define F_      36864

#define BM      16
#define THREADS 512
#define GT      64
#define NT2     64
#define NTILES  3                    // N = 24 (>= 18)
#define KT_TOT  (F_ / 16)            // 2304 global k-tiles

#define QSTRIDE 4100                 // uint2 words per quad row (4096 + 4 pad)
#define FE_STRIDE 1040               // bytes per feats row (512*2 + 16 pad)

// ---- fused kernel smem (bytes) ----
#define OBS_OFF   0
#define OBS_BYTES (4 * QSTRIDE * 8)          // 131200
#define WD_BYTES  (GT * 544)                 // 34816
#define IDX_BYTES (GT * 80)                  // 5120
#define BUF_BYTES (WD_BYTES + IDX_BYTES)     // 39936
#define WD0_OFF   (OBS_OFF + OBS_BYTES)      // 131200
#define IDX0_OFF  (WD0_OFF + WD_BYTES)
#define WD1_OFF   (WD0_OFF + BUF_BYTES)      // 171136
#define IDX1_OFF  (WD1_OFF + WD_BYTES)
#define FE_OFF    (WD1_OFF + BUF_BYTES)      // 211072
#define FE_BYTES  (16 * FE_STRIDE)           // 16640
#define SMEMA_BYTES (FE_OFF + FE_BYTES)      // 227712
#define RED_OFF   WD0_OFF                    // reduce stage aliases WD0 (24576 <= 39936)

// ---- obs-q kernel ----
#define OQ_KSPL   4
#define OQ_KPER   (OBS_ / OQ_KSPL)           // 1024
#define OQ_NCH    (OQ_KPER / 64)             // 16 chunks
#define OQ_STAGES 4
#define OQ_ASZ    (128 * 128)                // 16KB / stage
#define SMEMO_BYTES (OQ_STAGES * OQ_ASZ)     // 65536

// ---- device scratch ----
__device__ __align__(16) __half g_obsH[(size_t)B_ * OBS_];     // 16MB
__device__ uint2  g_gvfWl[(size_t)G_ * 64];                    // dup'd fp16 gvf weights
__device__ uint2  g_qfrag[(size_t)KT_TOT * NTILES * 32];       // qW in mma B-frag order
__device__ float  g_part[(size_t)OQ_KSPL * B_ * A_];           // obs-part split-K partials

// ================= helpers =================
__device__ __forceinline__ uint32_t smem_u32(const void* p) {
    return (uint32_t)__cvta_generic_to_shared(p);
}
__device__ __forceinline__ __half2 as_h2(unsigned u) { return *reinterpret_cast<__half2*>(&u); }

#define CPA16(dst, src) asm volatile("cp.async.cg.shared.global [%0], [%1], 16;" :: "r"(dst), "l"(src))
#define CPCOMMIT()      asm volatile("cp.async.commit_group;")
#define CPWAIT(n)       asm volatile("cp.async.wait_group %0;" :: "n"(n))

// ================= prep kernels =================
__global__ void prep_obsH(const float* __restrict__ obs) {
    int e = blockIdx.x * 256 + threadIdx.x;          // B_*OBS_/4
    float4 v = *reinterpret_cast<const float4*>(obs + (size_t)e * 4);
    __half2 a = __floats2half2_rn(v.x, v.y);
    __half2 b = __floats2half2_rn(v.z, v.w);
    uint2 o;
    o.x = *reinterpret_cast<unsigned*>(&a);
    o.y = *reinterpret_cast<unsigned*>(&b);
    *reinterpret_cast<uint2*>(g_obsH + (size_t)e * 4) = o;
}

__global__ void prep_gvfWl(const float* __restrict__ gvfW) {
    int e = blockIdx.x * 256 + threadIdx.x;
    if (e >= G_ * 64) return;
    int g = e >> 6, r = e & 63;
    int hh = r >> 5, p = (r >> 2) & 7, hp = r & 3;
    int h = hh * 4 + hp;
    float w0 = gvfW[(size_t)g * 128 + h * 16 + 2 * p];
    float w1 = gvfW[(size_t)g * 128 + h * 16 + 2 * p + 1];
    unsigned u0 = (unsigned)__half_as_ushort(__float2half(w0)); u0 |= u0 << 16;
    unsigned u1 = (unsigned)__half_as_ushort(__float2half(w1)); u1 |= u1 << 16;
    uint2 o; o.x = u0; o.y = u1;
    g_gvfWl[e] = o;
}

// qW -> mma.m16n8k16 B-fragment order (validated round 8)
__global__ void prep_qfrag(const float* __restrict__ qW) {
    int e = blockIdx.x * 256 + threadIdx.x;
    if (e >= KT_TOT * NTILES * 32) return;
    int lane = e & 31;
    int nt   = (e >> 5) % NTILES;
    int kt   = e / (32 * NTILES);
    int n = nt * 8 + (lane >> 2);
    int kb = kt * 16 + 2 * (lane & 3);
    uint2 o;
#pragma unroll
    for (int r = 0; r < 2; r++) {
        int k = kb + r * 8;
        float v0 = (n < A_) ? qW[(size_t)n * F_ + k]     : 0.f;
        float v1 = (n < A_) ? qW[(size_t)n * F_ + k + 1] : 0.f;
        unsigned u = (unsigned)__half_as_ushort(__float2half(v0))
                   | ((unsigned)__half_as_ushort(__float2half(v1)) << 16);
        if (r == 0) o.x = u; else o.y = u;
    }
    g_qfrag[e] = o;
}

// ================= obs-part q GEMM (HMMA, split-K partials) =================
__global__ __launch_bounds__(256, 1)
void obsq_kernel() {
    extern __shared__ char smem[];
    const int t    = threadIdx.x;
    const int wid  = t >> 5;
    const int lane = t & 31;
    const int mt   = blockIdx.x & 15;
    const int ks   = blockIdx.x >> 4;

    const uint32_t sA = smem_u32(smem);
    const int rowBase = mt * 128;
    const int kBase   = ks * OQ_KPER;

    auto load_chunk = [&](int c) {
        int st = c & (OQ_STAGES - 1);
        uint32_t base = sA + st * OQ_ASZ;
        int row = t >> 1;
        int hs  = t & 1;
        const __half* src = g_obsH + (size_t)(rowBase + row) * OBS_ + kBase + c * 64 + hs * 32;
        uint32_t rb = base + row * 128;
        uint32_t sw = (row & 7) << 4;
#pragma unroll
        for (int s = 0; s < 4; s++) {
            uint32_t byte = hs * 64 + s * 16;
            CPA16(rb + (byte ^ sw), src + s * 8);
        }
    };

    float acc[NTILES][4];
#pragma unroll
    for (int nt = 0; nt < NTILES; nt++)
#pragma unroll
        for (int r = 0; r < 4; r++) acc[nt][r] = 0.f;

#pragma unroll
    for (int c = 0; c < OQ_STAGES - 1; c++) { load_chunk(c); CPCOMMIT(); }

    const int warpM = wid * 16;
    const int lrow  = warpM + (lane & 15);
    const uint32_t lsw  = ((lrow & 7) << 4);
    const uint32_t lseg = ((lane >> 4) << 4);

    for (int c = 0; c < OQ_NCH; c++) {
        __syncthreads();
        if (c + OQ_STAGES - 1 < OQ_NCH) {
            load_chunk(c + OQ_STAGES - 1);
            CPCOMMIT();
            CPWAIT(OQ_STAGES - 1);
        } else {
            CPWAIT(0);
        }
        __syncthreads();

        uint32_t stBase = sA + (c & (OQ_STAGES - 1)) * OQ_ASZ + lrow * 128;

        uint2 bf[4][NTILES];
#pragma unroll
        for (int j = 0; j < 4; j++) {
            int gkt = kBase / 16 + c * 4 + j;
#pragma unroll
            for (int nt = 0; nt < NTILES; nt++)
                bf[j][nt] = __ldg(&g_qfrag[((size_t)gkt * NTILES + nt) * 32 + lane]);
        }

#pragma unroll
        for (int j = 0; j < 4; j++) {
            uint32_t a0, a1, a2, a3;
            uint32_t addr = stBase + ((j * 32 + lseg) ^ lsw);
            asm volatile("ldmatrix.sync.aligned.m8n8.x4.shared.b16 {%0,%1,%2,%3}, [%4];"
                         : "=r"(a0), "=r"(a1), "=r"(a2), "=r"(a3) : "r"(addr));
#pragma unroll
            for (int nt = 0; nt < NTILES; nt++) {
                asm volatile(
                    "mma.sync.aligned.m16n8k16.row.col.f32.f16.f16.f32 "
                    "{%0,%1,%2,%3}, {%4,%5,%6,%7}, {%8,%9}, {%0,%1,%2,%3};"
                    : "+f"(acc[nt][0]), "+f"(acc[nt][1]), "+f"(acc[nt][2]), "+f"(acc[nt][3])
                    : "r"(a0), "r"(a1), "r"(a2), "r"(a3),
                      "r"(bf[j][nt].x), "r"(bf[j][nt].y));
            }
        }
    }

    // plain stores (rows exclusive per CTA per split)
    float* dst = g_part + (size_t)ks * B_ * A_;
    const int gid = lane >> 2, tig = lane & 3;
    const int r0 = rowBase + warpM + gid;
    const int r1 = r0 + 8;
#pragma unroll
    for (int nt = 0; nt < NTILES; nt++) {
        int col = nt * 8 + 2 * tig;
        if (col < A_) {
            dst[(size_t)r0 * A_ + col] = acc[nt][0];
            dst[(size_t)r1 * A_ + col] = acc[nt][2];
        }
        if (col + 1 < A_) {
            dst[(size_t)r0 * A_ + col + 1] = acc[nt][1];
            dst[(size_t)r1 * A_ + col + 1] = acc[nt][3];
        }
    }
}

// ================= fused kernel: gather + GVF + gvf-part q GEMM =================
__global__ __launch_bounds__(THREADS, 1)
void gvf_fused_kernel(const float* __restrict__ obs,
                      const int*   __restrict__ gidx,
                      float* __restrict__ out) {
    extern __shared__ char smem[];
    uint2* sObs = reinterpret_cast<uint2*>(smem + OBS_OFF);

    const int t     = threadIdx.x;
    const int bBase = blockIdx.x * BM;

    const uint32_t wdA[2]  = { smem_u32(smem + WD0_OFF),  smem_u32(smem + WD1_OFF) };
    const uint32_t idxA[2] = { smem_u32(smem + IDX0_OFF), smem_u32(smem + IDX1_OFF) };

    // prologue: weight/idx groups for tiles 0,1
#pragma unroll
    for (int pt = 0; pt < 2; pt++) {
        const uint4* srcW = reinterpret_cast<const uint4*>(g_gvfWl) + (size_t)pt * 2048;
#pragma unroll
        for (int j = 0; j < 4; j++) {
            int e = j * THREADS + t;
            int gg = e >> 5, k = e & 31;
            CPA16(wdA[pt] + gg * 544 + k * 16, srcW + e);
        }
        if (t < 256) {
            int gg = t >> 2, j = t & 3;
            CPA16(idxA[pt] + gg * 80 + j * 16, gidx + (size_t)(pt * GT + gg) * 16 + j * 4);
        }
        CPCOMMIT();
    }

    // obs -> smem quads (fp16, 4 batch rows per uint2)
    for (int e = t; e < 4 * (OBS_ / 4); e += THREADS) {
        int q = e >> 10;
        int f = (e & 1023) * 4;
        float4 v0 = *reinterpret_cast<const float4*>(&obs[(size_t)(bBase + 4 * q + 0) * OBS_ + f]);
        float4 v1 = *reinterpret_cast<const float4*>(&obs[(size_t)(bBase + 4 * q + 1) * OBS_ + f]);
        float4 v2 = *reinterpret_cast<const float4*>(&obs[(size_t)(bBase + 4 * q + 2) * OBS_ + f]);
        float4 v3 = *reinterpret_cast<const float4*>(&obs[(size_t)(bBase + 4 * q + 3) * OBS_ + f]);
        uint2* dst = &sObs[q * QSTRIDE + f];
        __half2 a0 = __floats2half2_rn(v0.x, v1.x), b0 = __floats2half2_rn(v2.x, v3.x);
        __half2 a1 = __floats2half2_rn(v0.y, v1.y), b1 = __floats2half2_rn(v2.y, v3.y);
        __half2 a2 = __floats2half2_rn(v0.z, v1.z), b2 = __floats2half2_rn(v2.z, v3.z);
        __half2 a3 = __floats2half2_rn(v0.w, v1.w), b3 = __floats2half2_rn(v2.w, v3.w);
        uint4 s0, s1;
        s0.x = *reinterpret_cast<unsigned*>(&a0); s0.y = *reinterpret_cast<unsigned*>(&b0);
        s0.z = *reinterpret_cast<unsigned*>(&a1); s0.w = *reinterpret_cast<unsigned*>(&b1);
        s1.x = *reinterpret_cast<unsigned*>(&a2); s1.y = *reinterpret_cast<unsigned*>(&b2);
        s1.z = *reinterpret_cast<unsigned*>(&a3); s1.w = *reinterpret_cast<unsigned*>(&b3);
        *reinterpret_cast<uint4*>(dst)     = s0;
        *reinterpret_cast<uint4*>(dst + 2) = s1;
    }

    const int sp   = t & 3;
    const int gs   = (t >> 2) & 63;
    const int hh   = t >> 8;          // 0/1 -> heads 4hh..4hh+3
    const int wid  = t >> 5;          // 16 warps: K-slice cols [32w, 32w+32)
    const int lane = t & 31;
    const uint2* qrow = sObs + sp * QSTRIDE;
    const __half2 hz = __floats2half2_rn(0.f, 0.f);

    // feats store address (bytes)
    const uint32_t feSt = FE_OFF + (4 * sp) * FE_STRIDE + gs * 16 + hh * 8;
    // ldmatrix base address per lane
    const uint32_t feLd = smem_u32(smem + FE_OFF) + (lane & 15) * FE_STRIDE
                        + ((lane >> 4) << 4) + wid * 64;

    float acc[NTILES][4];
#pragma unroll
    for (int nt = 0; nt < NTILES; nt++)
#pragma unroll
        for (int r = 0; r < 4; r++) acc[nt][r] = 0.f;

    for (int ti = 0; ti < NT2; ti++) {
        const int sel = ti & 1;
        if (ti < NT2 - 1) { CPWAIT(1); } else { CPWAIT(0); }
        __syncthreads();   // S_A: weights(ti) visible; feats buffer free

        // prefetch B-frags for this tile's K-slice (L2)
        uint2 bf[2][NTILES];
        {
            int gkt = 256 + ti * 32 + 2 * wid;
#pragma unroll
            for (int j = 0; j < 2; j++)
#pragma unroll
                for (int nt = 0; nt < NTILES; nt++)
                    bf[j][nt] = __ldg(&g_qfrag[((size_t)(gkt + j) * NTILES + nt) * 32 + lane]);
        }

        const char* wdRow = smem + ((sel == 0) ? WD0_OFF : WD1_OFF) + gs * 544 + hh * 256;
        const int*  ip    = reinterpret_cast<const int*>(
                                smem + ((sel == 0) ? IDX0_OFF : IDX1_OFF)) + gs * 20;

        __half2 f01[4], f23[4];
#pragma unroll
        for (int j = 0; j < 4; j++) { f01[j] = hz; f23[j] = hz; }
#pragma unroll
        for (int c = 0; c < 2; c++) {
            int4 ia = *reinterpret_cast<const int4*>(ip + c * 8);
            int4 ib = *reinterpret_cast<const int4*>(ip + c * 8 + 4);
            int id[8] = { ia.x, ia.y, ia.z, ia.w, ib.x, ib.y, ib.z, ib.w };
#pragma unroll
            for (int pq = 0; pq < 4; pq++) {
                uint2 x0 = qrow[id[2 * pq]];
                uint2 x1 = qrow[id[2 * pq + 1]];
                int p = c * 4 + pq;
                uint4 wA = *reinterpret_cast<const uint4*>(wdRow + p * 32);
                uint4 wB = *reinterpret_cast<const uint4*>(wdRow + p * 32 + 16);
                f01[0] = __hfma2(as_h2(x0.x), as_h2(wA.x), f01[0]);
                f23[0] = __hfma2(as_h2(x0.y), as_h2(wA.x), f23[0]);
                f01[0] = __hfma2(as_h2(x1.x), as_h2(wA.y), f01[0]);
                f23[0] = __hfma2(as_h2(x1.y), as_h2(wA.y), f23[0]);
                f01[1] = __hfma2(as_h2(x0.x), as_h2(wA.z), f01[1]);
                f23[1] = __hfma2(as_h2(x0.y), as_h2(wA.z), f23[1]);
                f01[1] = __hfma2(as_h2(x1.x), as_h2(wA.w), f01[1]);
                f23[1] = __hfma2(as_h2(x1.y), as_h2(wA.w), f23[1]);
                f01[2] = __hfma2(as_h2(x0.x), as_h2(wB.x), f01[2]);
                f23[2] = __hfma2(as_h2(x0.y), as_h2(wB.x), f23[2]);
                f01[2] = __hfma2(as_h2(x1.x), as_h2(wB.y), f01[2]);
                f23[2] = __hfma2(as_h2(x1.y), as_h2(wB.y), f23[2]);
                f01[3] = __hfma2(as_h2(x0.x), as_h2(wB.z), f01[3]);
                f23[3] = __hfma2(as_h2(x0.y), as_h2(wB.z), f23[3]);
                f01[3] = __hfma2(as_h2(x1.x), as_h2(wB.w), f01[3]);
                f23[3] = __hfma2(as_h2(x1.y), as_h2(wB.w), f23[3]);
            }
        }

        // relu + pack + store feats tile rows 4sp..4sp+3
#pragma unroll
        for (int j = 0; j < 4; j++) { f01[j] = __hmax2(f01[j], hz); f23[j] = __hmax2(f23[j], hz); }
        {
            __half2 p0 = __lows2half2(f01[0], f01[1]);
            __half2 p1 = __lows2half2(f01[2], f01[3]);
            uint2 u; u.x = *reinterpret_cast<unsigned*>(&p0); u.y = *reinterpret_cast<unsigned*>(&p1);
            *reinterpret_cast<uint2*>(smem + feSt) = u;
        }
        {
            __half2 p0 = __highs2half2(f01[0], f01[1]);
            __half2 p1 = __highs2half2(f01[2], f01[3]);
            uint2 u; u.x = *reinterpret_cast<unsigned*>(&p0); u.y = *reinterpret_cast<unsigned*>(&p1);
            *reinterpret_cast<uint2*>(smem + feSt + FE_STRIDE) = u;
        }
        {
            __half2 p0 = __lows2half2(f23[0], f23[1]);
            __half2 p1 = __lows2half2(f23[2], f23[3]);
            uint2 u; u.x = *reinterpret_cast<unsigned*>(&p0); u.y = *reinterpret_cast<unsigned*>(&p1);
            *reinterpret_cast<uint2*>(smem + feSt + 2 * FE_STRIDE) = u;
        }
        {
            __half2 p0 = __highs2half2(f23[0], f23[1]);
            __half2 p1 = __highs2half2(f23[2], f23[3]);
            uint2 u; u.x = *reinterpret_cast<unsigned*>(&p0); u.y = *reinterpret_cast<unsigned*>(&p1);
            *reinterpret_cast<uint2*>(smem + feSt + 3 * FE_STRIDE) = u;
        }

        __syncthreads();   // S_B: feats visible; weights(sel) consumed

        if (ti + 2 < NT2) {
            const uint4* srcW = reinterpret_cast<const uint4*>(g_gvfWl) + (size_t)(ti + 2) * 2048;
#pragma unroll
            for (int j = 0; j < 4; j++) {
                int e = j * THREADS + t;
                int gg = e >> 5, k = e & 31;
                CPA16(wdA[sel] + gg * 544 + k * 16, srcW + e);
            }
            if (t < 256) {
                int gg = t >> 2, j = t & 3;
                CPA16(idxA[sel] + gg * 80 + j * 16,
                      gidx + (size_t)((ti + 2) * GT + gg) * 16 + j * 4);
            }
            CPCOMMIT();
        }

        // mma over this warp's 2 k-tiles
#pragma unroll
        for (int j = 0; j < 2; j++) {
            uint32_t a0, a1, a2, a3;
            asm volatile("ldmatrix.sync.aligned.m8n8.x4.shared.b16 {%0,%1,%2,%3}, [%4];"
                         : "=r"(a0), "=r"(a1), "=r"(a2), "=r"(a3) : "r"(feLd + j * 32));
#pragma unroll
            for (int nt = 0; nt < NTILES; nt++) {
                asm volatile(
                    "mma.sync.aligned.m16n8k16.row.col.f32.f16.f16.f32 "
                    "{%0,%1,%2,%3}, {%4,%5,%6,%7}, {%8,%9}, {%0,%1,%2,%3};"
                    : "+f"(acc[nt][0]), "+f"(acc[nt][1]), "+f"(acc[nt][2]), "+f"(acc[nt][3])
                    : "r"(a0), "r"(a1), "r"(a2), "r"(a3),
                      "r"(bf[j][nt].x), "r"(bf[j][nt].y));
            }
        }
    }

    // ---- cross-warp K reduction + obs-part fold ----
    __syncthreads();
    float* sRed = reinterpret_cast<float*>(smem + RED_OFF);   // [16w][16row][24col]
    {
        const int row0 = lane >> 2, c = lane & 3;
#pragma unroll
        for (int nt = 0; nt < NTILES; nt++) {
            int col = nt * 8 + 2 * c;
            *reinterpret_cast<float2*>(&sRed[(wid * 16 + row0) * 24 + col]) =
                make_float2(acc[nt][0], acc[nt][1]);
            *reinterpret_cast<float2*>(&sRed[(wid * 16 + row0 + 8) * 24 + col]) =
                make_float2(acc[nt][2], acc[nt][3]);
        }
    }
    __syncthreads();

    if (t < BM * A_) {
        int row = t / A_, a = t - row * A_;
        float s = 0.f;
#pragma unroll
        for (int w = 0; w < 16; w++)
            s += sRed[(w * 16 + row) * 24 + a];
        size_t o = (size_t)(bBase + row) * A_ + a;
#pragma unroll
        for (int ks = 0; ks < OQ_KSPL; ks++)
            s += g_part[(size_t)ks * B_ * A_ + o];
        out[o] = s;
    }
}

// ================= launch =================
extern "C" void kernel_launch(void* const* d_in, const int* in_sizes, int n_in,
                              void* d_out, int out_size) {
    const float* obs  = (const float*)d_in[0];
    const float* gvfW = (const float*)d_in[1];
    const float* qW   = (const float*)d_in[2];
    const int*   gidx = (const int*)d_in[3];
    float* out = (float*)d_out;

    prep_obsH<<<(B_ * OBS_ / 4) / 256, 256>>>(obs);
    prep_gvfWl<<<(G_ * 64 + 255) / 256, 256>>>(gvfW);
    prep_qfrag<<<(KT_TOT * NTILES * 32 + 255) / 256, 256>>>(qW);

    cudaFuncSetAttribute(obsq_kernel,
                         cudaFuncAttributeMaxDynamicSharedMemorySize, SMEMO_BYTES);
    obsq_kernel<<<16 * OQ_KSPL, 256, SMEMO_BYTES>>>();

    cudaFuncSetAttribute(gvf_fused_kernel,
                         cudaFuncAttributeMaxDynamicSharedMemorySize, SMEMA_BYTES);
    gvf_fused_kernel<<<B_ / BM, THREADS, SMEMA_BYTES>>>(obs, gidx, out);
}

// round 10
// speedup vs baseline: 1.6682x; 1.1469x over previous
#include <cuda_runtime.h>
#include <cuda_fp16.h>
#include <cstdint>

// Shapes (fixed)
#define B_      2048
#define OBS_    4096
#define G_      4096
#define I_      16
#define H_      8
#define A_      18
#define F_      36864

#define BM      16
#define THREADS 512
#define GT      64
#define NT2     64
#define NTILES  3                    // N = 24 (>= 18)
#define KT_TOT  (F_ / 16)            // 2304 global k-tiles

#define QSTRIDE 4100                 // uint2 words per quad row (4096 + 4 pad)
#define QROWB   (QSTRIDE * 8)        // bytes per quad row = 32800
#define FE_STRIDE 1040               // bytes per feats row (512*2 + 16 pad)

// ---- fused kernel smem (bytes) ----
#define OBS_OFF   0
#define OBS_BYTES (4 * QROWB)                // 131200
#define WD_BYTES  (GT * 544)                 // 34816
#define IDX_BYTES (GT * 80)                  // 5120
#define BUF_BYTES (WD_BYTES + IDX_BYTES)     // 39936
#define WD0_OFF   (OBS_OFF + OBS_BYTES)      // 131200
#define IDX0_OFF  (WD0_OFF + WD_BYTES)
#define WD1_OFF   (WD0_OFF + BUF_BYTES)      // 171136
#define IDX1_OFF  (WD1_OFF + WD_BYTES)
#define FE_OFF    (WD1_OFF + BUF_BYTES)      // 211072
#define FE_BYTES  (16 * FE_STRIDE)           // 16640
#define SMEMA_BYTES (FE_OFF + FE_BYTES)      // 227712
#define RED_OFF   WD0_OFF                    // reduce stage aliases WD0

// ---- device scratch ----
__device__ uint2  g_gvfWl[(size_t)G_ * 64];                    // dup'd fp16 gvf weights
__device__ uint2  g_qfrag[(size_t)KT_TOT * NTILES * 32];       // qW in mma B-frag order

// ================= helpers =================
__device__ __forceinline__ uint32_t smem_u32(const void* p) {
    return (uint32_t)__cvta_generic_to_shared(p);
}
__device__ __forceinline__ __half2 as_h2(unsigned u) { return *reinterpret_cast<__half2*>(&u); }

#define CPA16(dst, src) asm volatile("cp.async.cg.shared.global [%0], [%1], 16;" :: "r"(dst), "l"(src))
#define CPCOMMIT()      asm volatile("cp.async.commit_group;")
#define CPWAIT(n)       asm volatile("cp.async.wait_group %0;" :: "n"(n))

__device__ __forceinline__ uint32_t lds32(uint32_t addr) {
    uint32_t v;
    asm volatile("ld.shared.b32 %0, [%1];" : "=r"(v) : "r"(addr));
    return v;
}

// ================= prep kernels =================
__global__ void prep_gvfWl(const float* __restrict__ gvfW) {
    int e = blockIdx.x * 256 + threadIdx.x;
    if (e >= G_ * 64) return;
    int g = e >> 6, r = e & 63;
    int hh = r >> 5, p = (r >> 2) & 7, hp = r & 3;
    int h = hh * 4 + hp;
    float w0 = gvfW[(size_t)g * 128 + h * 16 + 2 * p];
    float w1 = gvfW[(size_t)g * 128 + h * 16 + 2 * p + 1];
    unsigned u0 = (unsigned)__half_as_ushort(__float2half(w0)); u0 |= u0 << 16;
    unsigned u1 = (unsigned)__half_as_ushort(__float2half(w1)); u1 |= u1 << 16;
    uint2 o; o.x = u0; o.y = u1;
    g_gvfWl[e] = o;
}

// qW -> mma.m16n8k16 B-fragment order (validated round 8)
__global__ void prep_qfrag(const float* __restrict__ qW) {
    int e = blockIdx.x * 256 + threadIdx.x;
    if (e >= KT_TOT * NTILES * 32) return;
    int lane = e & 31;
    int nt   = (e >> 5) % NTILES;
    int kt   = e / (32 * NTILES);
    int n = nt * 8 + (lane >> 2);
    int kb = kt * 16 + 2 * (lane & 3);
    uint2 o;
#pragma unroll
    for (int r = 0; r < 2; r++) {
        int k = kb + r * 8;
        float v0 = (n < A_) ? qW[(size_t)n * F_ + k]     : 0.f;
        float v1 = (n < A_) ? qW[(size_t)n * F_ + k + 1] : 0.f;
        unsigned u = (unsigned)__half_as_ushort(__float2half(v0))
                   | ((unsigned)__half_as_ushort(__float2half(v1)) << 16);
        if (r == 0) o.x = u; else o.y = u;
    }
    g_qfrag[e] = o;
}

// ================= fused kernel: gather + GVF + FULL q GEMM =================
__global__ __launch_bounds__(THREADS, 1)
void gvf_fused_kernel(const float* __restrict__ obs,
                      const int*   __restrict__ gidx,
                      float* __restrict__ out) {
    extern __shared__ char smem[];
    uint2* sObs = reinterpret_cast<uint2*>(smem + OBS_OFF);

    const int t     = threadIdx.x;
    const int bBase = blockIdx.x * BM;

    const uint32_t wdA[2]  = { smem_u32(smem + WD0_OFF),  smem_u32(smem + WD1_OFF) };
    const uint32_t idxA[2] = { smem_u32(smem + IDX0_OFF), smem_u32(smem + IDX1_OFF) };

    // prologue: weight/idx groups for tiles 0,1
#pragma unroll
    for (int pt = 0; pt < 2; pt++) {
        const uint4* srcW = reinterpret_cast<const uint4*>(g_gvfWl) + (size_t)pt * 2048;
#pragma unroll
        for (int j = 0; j < 4; j++) {
            int e = j * THREADS + t;
            int gg = e >> 5, k = e & 31;
            CPA16(wdA[pt] + gg * 544 + k * 16, srcW + e);
        }
        if (t < 256) {
            int gg = t >> 2, j = t & 3;
            CPA16(idxA[pt] + gg * 80 + j * 16, gidx + (size_t)(pt * GT + gg) * 16 + j * 4);
        }
        CPCOMMIT();
    }

    // phase 0: obs -> smem quads (fp16, 4 batch rows per uint2)
    for (int e = t; e < 4 * (OBS_ / 4); e += THREADS) {
        int q = e >> 10;
        int f = (e & 1023) * 4;
        float4 v0 = *reinterpret_cast<const float4*>(&obs[(size_t)(bBase + 4 * q + 0) * OBS_ + f]);
        float4 v1 = *reinterpret_cast<const float4*>(&obs[(size_t)(bBase + 4 * q + 1) * OBS_ + f]);
        float4 v2 = *reinterpret_cast<const float4*>(&obs[(size_t)(bBase + 4 * q + 2) * OBS_ + f]);
        float4 v3 = *reinterpret_cast<const float4*>(&obs[(size_t)(bBase + 4 * q + 3) * OBS_ + f]);
        uint2* dst = &sObs[q * QSTRIDE + f];
        __half2 a0 = __floats2half2_rn(v0.x, v1.x), b0 = __floats2half2_rn(v2.x, v3.x);
        __half2 a1 = __floats2half2_rn(v0.y, v1.y), b1 = __floats2half2_rn(v2.y, v3.y);
        __half2 a2 = __floats2half2_rn(v0.z, v1.z), b2 = __floats2half2_rn(v2.z, v3.z);
        __half2 a3 = __floats2half2_rn(v0.w, v1.w), b3 = __floats2half2_rn(v2.w, v3.w);
        uint4 s0, s1;
        s0.x = *reinterpret_cast<unsigned*>(&a0); s0.y = *reinterpret_cast<unsigned*>(&b0);
        s0.z = *reinterpret_cast<unsigned*>(&a1); s0.w = *reinterpret_cast<unsigned*>(&b1);
        s1.x = *reinterpret_cast<unsigned*>(&a2); s1.y = *reinterpret_cast<unsigned*>(&b2);
        s1.z = *reinterpret_cast<unsigned*>(&a3); s1.w = *reinterpret_cast<unsigned*>(&b3);
        *reinterpret_cast<uint4*>(dst)     = s0;
        *reinterpret_cast<uint4*>(dst + 2) = s1;
    }
    __syncthreads();   // sObs ready for obs-part mma

    const int sp   = t & 3;
    const int gs   = (t >> 2) & 63;
    const int hh   = t >> 8;
    const int wid  = t >> 5;          // 16 warps
    const int lane = t & 31;
    const uint2* qrow = sObs + sp * QSTRIDE;
    const __half2 hz = __floats2half2_rn(0.f, 0.f);

    float acc[NTILES][4];
#pragma unroll
    for (int nt = 0; nt < NTILES; nt++)
#pragma unroll
        for (int r = 0; r < 4; r++) acc[nt][r] = 0.f;

    // ======= obs-part q GEMM straight from quad smem =======
    // lane (gid,tig): rows {gid, gid+8}, cols {c0, c0+1, c0+8, c0+9}
    {
        const int gid = lane >> 2, tig = lane & 3;
        const uint32_t obsA = smem_u32(sObs);
        // quad of row gid: gid>>2; half-pair select: rows (gid&3)<2 -> u.x else u.y
        const uint32_t aQ0 = obsA + (uint32_t)(gid >> 2) * QROWB + (((gid & 3) >> 1) << 2);
        const uint32_t aQ1 = aQ0 + 2 * QROWB;   // row gid+8
        const uint32_t psel = (gid & 1) ? 0x7632u : 0x5410u;

        for (int j = 0; j < 16; j++) {
            const int gkt = wid * 16 + j;            // obs k-tiles 0..255
            const uint32_t cb = (uint32_t)(gkt * 16 + 2 * tig) * 8;

            uint2 bf[NTILES];
#pragma unroll
            for (int nt = 0; nt < NTILES; nt++)
                bf[nt] = __ldg(&g_qfrag[((size_t)gkt * NTILES + nt) * 32 + lane]);

            uint32_t l00 = lds32(aQ0 + cb),      l01 = lds32(aQ0 + cb + 8);
            uint32_t l10 = lds32(aQ1 + cb),      l11 = lds32(aQ1 + cb + 8);
            uint32_t l02 = lds32(aQ0 + cb + 64), l03 = lds32(aQ0 + cb + 72);
            uint32_t l12 = lds32(aQ1 + cb + 64), l13 = lds32(aQ1 + cb + 72);
            uint32_t a0 = __byte_perm(l00, l01, psel);
            uint32_t a1 = __byte_perm(l10, l11, psel);
            uint32_t a2 = __byte_perm(l02, l03, psel);
            uint32_t a3 = __byte_perm(l12, l13, psel);
#pragma unroll
            for (int nt = 0; nt < NTILES; nt++) {
                asm volatile(
                    "mma.sync.aligned.m16n8k16.row.col.f32.f16.f16.f32 "
                    "{%0,%1,%2,%3}, {%4,%5,%6,%7}, {%8,%9}, {%0,%1,%2,%3};"
                    : "+f"(acc[nt][0]), "+f"(acc[nt][1]), "+f"(acc[nt][2]), "+f"(acc[nt][3])
                    : "r"(a0), "r"(a1), "r"(a2), "r"(a3),
                      "r"(bf[nt].x), "r"(bf[nt].y));
            }
        }
    }

    // feats store address (bytes)
    const uint32_t feSt = FE_OFF + (4 * sp) * FE_STRIDE + gs * 16 + hh * 8;
    const uint32_t feLd = smem_u32(smem + FE_OFF) + (lane & 15) * FE_STRIDE
                        + ((lane >> 4) << 4) + wid * 64;

    // ======= gvf tiles =======
    for (int ti = 0; ti < NT2; ti++) {
        const int sel = ti & 1;
        if (ti < NT2 - 1) { CPWAIT(1); } else { CPWAIT(0); }
        __syncthreads();   // S_A: weights(ti) visible; feats buffer free

        uint2 bf[2][NTILES];
        {
            int gkt = 256 + ti * 32 + 2 * wid;
#pragma unroll
            for (int j = 0; j < 2; j++)
#pragma unroll
                for (int nt = 0; nt < NTILES; nt++)
                    bf[j][nt] = __ldg(&g_qfrag[((size_t)(gkt + j) * NTILES + nt) * 32 + lane]);
        }

        const char* wdRow = smem + ((sel == 0) ? WD0_OFF : WD1_OFF) + gs * 544 + hh * 256;
        const int*  ip    = reinterpret_cast<const int*>(
                                smem + ((sel == 0) ? IDX0_OFF : IDX1_OFF)) + gs * 20;

        __half2 f01[4], f23[4];
#pragma unroll
        for (int j = 0; j < 4; j++) { f01[j] = hz; f23[j] = hz; }
#pragma unroll
        for (int c = 0; c < 2; c++) {
            int4 ia = *reinterpret_cast<const int4*>(ip + c * 8);
            int4 ib = *reinterpret_cast<const int4*>(ip + c * 8 + 4);
            int id[8] = { ia.x, ia.y, ia.z, ia.w, ib.x, ib.y, ib.z, ib.w };
#pragma unroll
            for (int pq = 0; pq < 4; pq++) {
                uint2 x0 = qrow[id[2 * pq]];
                uint2 x1 = qrow[id[2 * pq + 1]];
                int p = c * 4 + pq;
                uint4 wA = *reinterpret_cast<const uint4*>(wdRow + p * 32);
                uint4 wB = *reinterpret_cast<const uint4*>(wdRow + p * 32 + 16);
                f01[0] = __hfma2(as_h2(x0.x), as_h2(wA.x), f01[0]);
                f23[0] = __hfma2(as_h2(x0.y), as_h2(wA.x), f23[0]);
                f01[0] = __hfma2(as_h2(x1.x), as_h2(wA.y), f01[0]);
                f23[0] = __hfma2(as_h2(x1.y), as_h2(wA.y), f23[0]);
                f01[1] = __hfma2(as_h2(x0.x), as_h2(wA.z), f01[1]);
                f23[1] = __hfma2(as_h2(x0.y), as_h2(wA.z), f23[1]);
                f01[1] = __hfma2(as_h2(x1.x), as_h2(wA.w), f01[1]);
                f23[1] = __hfma2(as_h2(x1.y), as_h2(wA.w), f23[1]);
                f01[2] = __hfma2(as_h2(x0.x), as_h2(wB.x), f01[2]);
                f23[2] = __hfma2(as_h2(x0.y), as_h2(wB.x), f23[2]);
                f01[2] = __hfma2(as_h2(x1.x), as_h2(wB.y), f01[2]);
                f23[2] = __hfma2(as_h2(x1.y), as_h2(wB.y), f23[2]);
                f01[3] = __hfma2(as_h2(x0.x), as_h2(wB.z), f01[3]);
                f23[3] = __hfma2(as_h2(x0.y), as_h2(wB.z), f23[3]);
                f01[3] = __hfma2(as_h2(x1.x), as_h2(wB.w), f01[3]);
                f23[3] = __hfma2(as_h2(x1.y), as_h2(wB.w), f23[3]);
            }
        }

#pragma unroll
        for (int j = 0; j < 4; j++) { f01[j] = __hmax2(f01[j], hz); f23[j] = __hmax2(f23[j], hz); }
        {
            __half2 p0 = __lows2half2(f01[0], f01[1]);
            __half2 p1 = __lows2half2(f01[2], f01[3]);
            uint2 u; u.x = *reinterpret_cast<unsigned*>(&p0); u.y = *reinterpret_cast<unsigned*>(&p1);
            *reinterpret_cast<uint2*>(smem + feSt) = u;
        }
        {
            __half2 p0 = __highs2half2(f01[0], f01[1]);
            __half2 p1 = __highs2half2(f01[2], f01[3]);
            uint2 u; u.x = *reinterpret_cast<unsigned*>(&p0); u.y = *reinterpret_cast<unsigned*>(&p1);
            *reinterpret_cast<uint2*>(smem + feSt + FE_STRIDE) = u;
        }
        {
            __half2 p0 = __lows2half2(f23[0], f23[1]);
            __half2 p1 = __lows2half2(f23[2], f23[3]);
            uint2 u; u.x = *reinterpret_cast<unsigned*>(&p0); u.y = *reinterpret_cast<unsigned*>(&p1);
            *reinterpret_cast<uint2*>(smem + feSt + 2 * FE_STRIDE) = u;
        }
        {
            __half2 p0 = __highs2half2(f23[0], f23[1]);
            __half2 p1 = __highs2half2(f23[2], f23[3]);
            uint2 u; u.x = *reinterpret_cast<unsigned*>(&p0); u.y = *reinterpret_cast<unsigned*>(&p1);
            *reinterpret_cast<uint2*>(smem + feSt + 3 * FE_STRIDE) = u;
        }

        __syncthreads();   // S_B: feats visible; weights(sel) consumed

        if (ti + 2 < NT2) {
            const uint4* srcW = reinterpret_cast<const uint4*>(g_gvfWl) + (size_t)(ti + 2) * 2048;
#pragma unroll
            for (int j = 0; j < 4; j++) {
                int e = j * THREADS + t;
                int gg = e >> 5, k = e & 31;
                CPA16(wdA[sel] + gg * 544 + k * 16, srcW + e);
            }
            if (t < 256) {
                int gg = t >> 2, j = t & 3;
                CPA16(idxA[sel] + gg * 80 + j * 16,
                      gidx + (size_t)((ti + 2) * GT + gg) * 16 + j * 4);
            }
            CPCOMMIT();
        }

        // mma over this warp's 2 gvf k-tiles
#pragma unroll
        for (int j = 0; j < 2; j++) {
            uint32_t a0, a1, a2, a3;
            asm volatile("ldmatrix.sync.aligned.m8n8.x4.shared.b16 {%0,%1,%2,%3}, [%4];"
                         : "=r"(a0), "=r"(a1), "=r"(a2), "=r"(a3) : "r"(feLd + j * 32));
#pragma unroll
            for (int nt = 0; nt < NTILES; nt++) {
                asm volatile(
                    "mma.sync.aligned.m16n8k16.row.col.f32.f16.f16.f32 "
                    "{%0,%1,%2,%3}, {%4,%5,%6,%7}, {%8,%9}, {%0,%1,%2,%3};"
                    : "+f"(acc[nt][0]), "+f"(acc[nt][1]), "+f"(acc[nt][2]), "+f"(acc[nt][3])
                    : "r"(a0), "r"(a1), "r"(a2), "r"(a3),
                      "r"(bf[j][nt].x), "r"(bf[j][nt].y));
            }
        }
    }

    // ---- cross-warp K reduction ----
    __syncthreads();
    float* sRed = reinterpret_cast<float*>(smem + RED_OFF);   // [16w][16row][24col]
    {
        const int row0 = lane >> 2, c = lane & 3;
#pragma unroll
        for (int nt = 0; nt < NTILES; nt++) {
            int col = nt * 8 + 2 * c;
            *reinterpret_cast<float2*>(&sRed[(wid * 16 + row0) * 24 + col]) =
                make_float2(acc[nt][0], acc[nt][1]);
            *reinterpret_cast<float2*>(&sRed[(wid * 16 + row0 + 8) * 24 + col]) =
                make_float2(acc[nt][2], acc[nt][3]);
        }
    }
    __syncthreads();

    if (t < BM * A_) {
        int row = t / A_, a = t - row * A_;
        float s = 0.f;
#pragma unroll
        for (int w = 0; w < 16; w++)
            s += sRed[(w * 16 + row) * 24 + a];
        out[(size_t)(bBase + row) * A_ + a] = s;
    }
}

// ================= launch =================
extern "C" void kernel_launch(void* const* d_in, const int* in_sizes, int n_in,
                              void* d_out, int out_size) {
    const float* obs  = (const float*)d_in[0];
    const float* gvfW = (const float*)d_in[1];
    const float* qW   = (const float*)d_in[2];
    const int*   gidx = (const int*)d_in[3];
    float* out = (float*)d_out;

    prep_gvfWl<<<(G_ * 64 + 255) / 256, 256>>>(gvfW);
    prep_qfrag<<<(KT_TOT * NTILES * 32 + 255) / 256, 256>>>(qW);

    cudaFuncSetAttribute(gvf_fused_kernel,
                         cudaFuncAttributeMaxDynamicSharedMemorySize, SMEMA_BYTES);
    gvf_fused_kernel<<<B_ / BM, THREADS, SMEMA_BYTES>>>(obs, gidx, out);
}

// round 11
// speedup vs baseline: 2.1895x; 1.3125x over previous
#include <cuda_runtime.h>
#include <cuda_fp16.h>
#include <cstdint>

// Shapes (fixed)
#define B_      2048
#define OBS_    4096
#define G_      4096
#define I_      16
#define H_      8
#define A_      18
#define F_      36864

#define BM      16
#define THREADS 512
#define GT      64
#define NT2     64
#define NTILES  3                    // N = 24 (>= 18)
#define KT_TOT  (F_ / 16)            // 2304 global k-tiles

#define QSTRIDE 4100                 // uint2 words per quad row (4096 + 4 pad)
#define QROWB   (QSTRIDE * 8)        // bytes per quad row = 32800
#define FE_STRIDE 1040               // bytes per feats row (512*2 + 16 pad)

// weight tile row: [hh0: 128B][16B pad][hh1: 128B][16B pad] = 288B
#define WROWB   288

// ---- fused kernel smem (bytes) ----
#define OBS_OFF   0
#define OBS_BYTES (4 * QROWB)                // 131200
#define WD_BYTES  (GT * WROWB)               // 18432
#define IDX_BYTES (GT * 80)                  // 5120
#define BUF_BYTES (WD_BYTES + IDX_BYTES)     // 23552
#define WD0_OFF   (OBS_OFF + OBS_BYTES)      // 131200
#define IDX0_OFF  (WD0_OFF + WD_BYTES)       // 149632
#define WD1_OFF   (WD0_OFF + BUF_BYTES)      // 154752
#define IDX1_OFF  (WD1_OFF + WD_BYTES)       // 173184
#define FE_OFF    (WD1_OFF + BUF_BYTES)      // 178304
#define FE_BYTES  (16 * FE_STRIDE)           // 16640
#define SMEMA_BYTES (FE_OFF + FE_BYTES)      // 194944
#define RED_OFF   WD0_OFF                    // 24576B, spans WD0+IDX0(+1KB WD1), post-barrier

// ---- device scratch ----
__device__ uint4  g_gvfWs[(size_t)G_ * 16];                    // fp16 weights, frag order
__device__ uint2  g_qfrag[(size_t)KT_TOT * NTILES * 32];       // qW in mma B-frag order

// ================= helpers =================
__device__ __forceinline__ uint32_t smem_u32(const void* p) {
    return (uint32_t)__cvta_generic_to_shared(p);
}
__device__ __forceinline__ __half2 as_h2(unsigned u) { return *reinterpret_cast<__half2*>(&u); }

#define CPA16(dst, src) asm volatile("cp.async.cg.shared.global [%0], [%1], 16;" :: "r"(dst), "l"(src))
#define CPCOMMIT()      asm volatile("cp.async.commit_group;")
#define CPWAIT(n)       asm volatile("cp.async.wait_group %0;" :: "n"(n))

__device__ __forceinline__ uint32_t lds32(uint32_t addr) {
    uint32_t v;
    asm volatile("ld.shared.b32 %0, [%1];" : "=r"(v) : "r"(addr));
    return v;
}

// ================= prep kernels =================
// weights: g_gvfWs[g*16 + hh*8 + p] = uint4 of 8 halfs:
//   {h=4hh+0:(w[2p],w[2p+1]), h=4hh+1:(..), h=4hh+2:(..), h=4hh+3:(..)}
__global__ void prep_gvfWs(const float* __restrict__ gvfW) {
    int e = blockIdx.x * 256 + threadIdx.x;
    if (e >= G_ * 16) return;
    int g = e >> 4, r = e & 15;
    int hh = r >> 3, p = r & 7;
    unsigned rr[4];
#pragma unroll
    for (int hp = 0; hp < 4; hp++) {
        int h = 4 * hh + hp;
        unsigned w0 = (unsigned)__half_as_ushort(__float2half(gvfW[(size_t)g * 128 + h * 16 + 2 * p]));
        unsigned w1 = (unsigned)__half_as_ushort(__float2half(gvfW[(size_t)g * 128 + h * 16 + 2 * p + 1]));
        rr[hp] = w0 | (w1 << 16);
    }
    uint4 o; o.x = rr[0]; o.y = rr[1]; o.z = rr[2]; o.w = rr[3];
    g_gvfWs[e] = o;
}

// qW -> mma.m16n8k16 B-fragment order (validated round 8)
__global__ void prep_qfrag(const float* __restrict__ qW) {
    int e = blockIdx.x * 256 + threadIdx.x;
    if (e >= KT_TOT * NTILES * 32) return;
    int lane = e & 31;
    int nt   = (e >> 5) % NTILES;
    int kt   = e / (32 * NTILES);
    int n = nt * 8 + (lane >> 2);
    int kb = kt * 16 + 2 * (lane & 3);
    uint2 o;
#pragma unroll
    for (int r = 0; r < 2; r++) {
        int k = kb + r * 8;
        float v0 = (n < A_) ? qW[(size_t)n * F_ + k]     : 0.f;
        float v1 = (n < A_) ? qW[(size_t)n * F_ + k + 1] : 0.f;
        unsigned u = (unsigned)__half_as_ushort(__float2half(v0))
                   | ((unsigned)__half_as_ushort(__float2half(v1)) << 16);
        if (r == 0) o.x = u; else o.y = u;
    }
    g_qfrag[e] = o;
}

// weight cp.async dst offset within a tile buffer
__device__ __forceinline__ uint32_t wdst(int e) {
    int gg = e >> 4, k = e & 15;
    return (uint32_t)(gg * WROWB + ((k < 8) ? k * 16 : 144 + (k - 8) * 16));
}

// ================= fused kernel: gather + GVF + FULL q GEMM =================
__global__ __launch_bounds__(THREADS, 1)
void gvf_fused_kernel(const float* __restrict__ obs,
                      const int*   __restrict__ gidx,
                      float* __restrict__ out) {
    extern __shared__ char smem[];
    uint2* sObs = reinterpret_cast<uint2*>(smem + OBS_OFF);

    const int t     = threadIdx.x;
    const int bBase = blockIdx.x * BM;

    const uint32_t wdA[2]  = { smem_u32(smem + WD0_OFF),  smem_u32(smem + WD1_OFF) };
    const uint32_t idxA[2] = { smem_u32(smem + IDX0_OFF), smem_u32(smem + IDX1_OFF) };

    // prologue: weight/idx groups for tiles 0,1
#pragma unroll
    for (int pt = 0; pt < 2; pt++) {
        const uint4* srcW = reinterpret_cast<const uint4*>(g_gvfWs) + (size_t)pt * 1024;
#pragma unroll
        for (int j = 0; j < 2; j++) {
            int e = j * THREADS + t;
            CPA16(wdA[pt] + wdst(e), srcW + e);
        }
        if (t < 256) {
            int gg = t >> 2, j = t & 3;
            CPA16(idxA[pt] + gg * 80 + j * 16, gidx + (size_t)(pt * GT + gg) * 16 + j * 4);
        }
        CPCOMMIT();
    }

    // phase 0: obs -> smem quads (fp16, 4 batch rows per uint2)
    for (int e = t; e < 4 * (OBS_ / 4); e += THREADS) {
        int q = e >> 10;
        int f = (e & 1023) * 4;
        float4 v0 = *reinterpret_cast<const float4*>(&obs[(size_t)(bBase + 4 * q + 0) * OBS_ + f]);
        float4 v1 = *reinterpret_cast<const float4*>(&obs[(size_t)(bBase + 4 * q + 1) * OBS_ + f]);
        float4 v2 = *reinterpret_cast<const float4*>(&obs[(size_t)(bBase + 4 * q + 2) * OBS_ + f]);
        float4 v3 = *reinterpret_cast<const float4*>(&obs[(size_t)(bBase + 4 * q + 3) * OBS_ + f]);
        uint2* dst = &sObs[q * QSTRIDE + f];
        __half2 a0 = __floats2half2_rn(v0.x, v1.x), b0 = __floats2half2_rn(v2.x, v3.x);
        __half2 a1 = __floats2half2_rn(v0.y, v1.y), b1 = __floats2half2_rn(v2.y, v3.y);
        __half2 a2 = __floats2half2_rn(v0.z, v1.z), b2 = __floats2half2_rn(v2.z, v3.z);
        __half2 a3 = __floats2half2_rn(v0.w, v1.w), b3 = __floats2half2_rn(v2.w, v3.w);
        uint4 s0, s1;
        s0.x = *reinterpret_cast<unsigned*>(&a0); s0.y = *reinterpret_cast<unsigned*>(&b0);
        s0.z = *reinterpret_cast<unsigned*>(&a1); s0.w = *reinterpret_cast<unsigned*>(&b1);
        s1.x = *reinterpret_cast<unsigned*>(&a2); s1.y = *reinterpret_cast<unsigned*>(&b2);
        s1.z = *reinterpret_cast<unsigned*>(&a3); s1.w = *reinterpret_cast<unsigned*>(&b3);
        *reinterpret_cast<uint4*>(dst)     = s0;
        *reinterpret_cast<uint4*>(dst + 2) = s1;
    }
    __syncthreads();   // sObs ready for obs-part mma

    // thread roles: hh pairs adjacent (lanes l, l+4 share (sp,gs) -> gather merge)
    const int sp   = t & 3;
    const int hh   = (t >> 2) & 1;
    const int gs   = t >> 3;
    const int wid  = t >> 5;          // 16 warps
    const int lane = t & 31;
    const uint2* qrow = sObs + sp * QSTRIDE;
    const __half2 hz = __floats2half2_rn(0.f, 0.f);

    float acc[NTILES][4];
#pragma unroll
    for (int nt = 0; nt < NTILES; nt++)
#pragma unroll
        for (int r = 0; r < 4; r++) acc[nt][r] = 0.f;

    // ======= obs-part q GEMM straight from quad smem =======
    {
        const int gid = lane >> 2, tig = lane & 3;
        const uint32_t obsA = smem_u32(sObs);
        const uint32_t aQ0 = obsA + (uint32_t)(gid >> 2) * QROWB + (((gid & 3) >> 1) << 2);
        const uint32_t aQ1 = aQ0 + 2 * QROWB;   // row gid+8
        const uint32_t psel = (gid & 1) ? 0x7632u : 0x5410u;

        for (int j = 0; j < 16; j++) {
            const int gkt = wid * 16 + j;            // obs k-tiles 0..255
            const uint32_t cb = (uint32_t)(gkt * 16 + 2 * tig) * 8;

            uint2 bf[NTILES];
#pragma unroll
            for (int nt = 0; nt < NTILES; nt++)
                bf[nt] = __ldg(&g_qfrag[((size_t)gkt * NTILES + nt) * 32 + lane]);

            uint32_t l00 = lds32(aQ0 + cb),      l01 = lds32(aQ0 + cb + 8);
            uint32_t l10 = lds32(aQ1 + cb),      l11 = lds32(aQ1 + cb + 8);
            uint32_t l02 = lds32(aQ0 + cb + 64), l03 = lds32(aQ0 + cb + 72);
            uint32_t l12 = lds32(aQ1 + cb + 64), l13 = lds32(aQ1 + cb + 72);
            uint32_t a0 = __byte_perm(l00, l01, psel);
            uint32_t a1 = __byte_perm(l10, l11, psel);
            uint32_t a2 = __byte_perm(l02, l03, psel);
            uint32_t a3 = __byte_perm(l12, l13, psel);
#pragma unroll
            for (int nt = 0; nt < NTILES; nt++) {
                asm volatile(
                    "mma.sync.aligned.m16n8k16.row.col.f32.f16.f16.f32 "
                    "{%0,%1,%2,%3}, {%4,%5,%6,%7}, {%8,%9}, {%0,%1,%2,%3};"
                    : "+f"(acc[nt][0]), "+f"(acc[nt][1]), "+f"(acc[nt][2]), "+f"(acc[nt][3])
                    : "r"(a0), "r"(a1), "r"(a2), "r"(a3),
                      "r"(bf[nt].x), "r"(bf[nt].y));
            }
        }
    }

    // feats store address (bytes)
    const uint32_t feSt = FE_OFF + (4 * sp) * FE_STRIDE + gs * 16 + hh * 8;
    const uint32_t feLd = smem_u32(smem + FE_OFF) + (lane & 15) * FE_STRIDE
                        + ((lane >> 4) << 4) + wid * 64;

    // ======= gvf tiles =======
    for (int ti = 0; ti < NT2; ti++) {
        const int sel = ti & 1;
        if (ti < NT2 - 1) { CPWAIT(1); } else { CPWAIT(0); }
        __syncthreads();   // S_A: weights(ti) visible; feats buffer free

        uint2 bf[2][NTILES];
        {
            int gkt = 256 + ti * 32 + 2 * wid;
#pragma unroll
            for (int j = 0; j < 2; j++)
#pragma unroll
                for (int nt = 0; nt < NTILES; nt++)
                    bf[j][nt] = __ldg(&g_qfrag[((size_t)(gkt + j) * NTILES + nt) * 32 + lane]);
        }

        const char* wdRow = smem + ((sel == 0) ? WD0_OFF : WD1_OFF) + gs * WROWB + hh * 144;
        const int*  ip    = reinterpret_cast<const int*>(
                                smem + ((sel == 0) ? IDX0_OFF : IDX1_OFF)) + gs * 20;

        __half2 f01[4], f23[4];
#pragma unroll
        for (int j = 0; j < 4; j++) { f01[j] = hz; f23[j] = hz; }
#pragma unroll
        for (int c = 0; c < 2; c++) {
            int4 ia = *reinterpret_cast<const int4*>(ip + c * 8);
            int4 ib = *reinterpret_cast<const int4*>(ip + c * 8 + 4);
            int id[8] = { ia.x, ia.y, ia.z, ia.w, ib.x, ib.y, ib.z, ib.w };
#pragma unroll
            for (int pq = 0; pq < 4; pq++) {
                uint2 x0 = qrow[id[2 * pq]];          // merged across hh pair
                uint2 x1 = qrow[id[2 * pq + 1]];
                int p = c * 4 + pq;
                uint4 wv = *reinterpret_cast<const uint4*>(wdRow + p * 16);
                // hp0
                {
                    uint32_t w0d = __byte_perm(wv.x, wv.x, 0x1010);
                    uint32_t w1d = __byte_perm(wv.x, wv.x, 0x3232);
                    f01[0] = __hfma2(as_h2(x0.x), as_h2(w0d), f01[0]);
                    f23[0] = __hfma2(as_h2(x0.y), as_h2(w0d), f23[0]);
                    f01[0] = __hfma2(as_h2(x1.x), as_h2(w1d), f01[0]);
                    f23[0] = __hfma2(as_h2(x1.y), as_h2(w1d), f23[0]);
                }
                // hp1
                {
                    uint32_t w0d = __byte_perm(wv.y, wv.y, 0x1010);
                    uint32_t w1d = __byte_perm(wv.y, wv.y, 0x3232);
                    f01[1] = __hfma2(as_h2(x0.x), as_h2(w0d), f01[1]);
                    f23[1] = __hfma2(as_h2(x0.y), as_h2(w0d), f23[1]);
                    f01[1] = __hfma2(as_h2(x1.x), as_h2(w1d), f01[1]);
                    f23[1] = __hfma2(as_h2(x1.y), as_h2(w1d), f23[1]);
                }
                // hp2
                {
                    uint32_t w0d = __byte_perm(wv.z, wv.z, 0x1010);
                    uint32_t w1d = __byte_perm(wv.z, wv.z, 0x3232);
                    f01[2] = __hfma2(as_h2(x0.x), as_h2(w0d), f01[2]);
                    f23[2] = __hfma2(as_h2(x0.y), as_h2(w0d), f23[2]);
                    f01[2] = __hfma2(as_h2(x1.x), as_h2(w1d), f01[2]);
                    f23[2] = __hfma2(as_h2(x1.y), as_h2(w1d), f23[2]);
                }
                // hp3
                {
                    uint32_t w0d = __byte_perm(wv.w, wv.w, 0x1010);
                    uint32_t w1d = __byte_perm(wv.w, wv.w, 0x3232);
                    f01[3] = __hfma2(as_h2(x0.x), as_h2(w0d), f01[3]);
                    f23[3] = __hfma2(as_h2(x0.y), as_h2(w0d), f23[3]);
                    f01[3] = __hfma2(as_h2(x1.x), as_h2(w1d), f01[3]);
                    f23[3] = __hfma2(as_h2(x1.y), as_h2(w1d), f23[3]);
                }
            }
        }

#pragma unroll
        for (int j = 0; j < 4; j++) { f01[j] = __hmax2(f01[j], hz); f23[j] = __hmax2(f23[j], hz); }
        {
            __half2 p0 = __lows2half2(f01[0], f01[1]);
            __half2 p1 = __lows2half2(f01[2], f01[3]);
            uint2 u; u.x = *reinterpret_cast<unsigned*>(&p0); u.y = *reinterpret_cast<unsigned*>(&p1);
            *reinterpret_cast<uint2*>(smem + feSt) = u;
        }
        {
            __half2 p0 = __highs2half2(f01[0], f01[1]);
            __half2 p1 = __highs2half2(f01[2], f01[3]);
            uint2 u; u.x = *reinterpret_cast<unsigned*>(&p0); u.y = *reinterpret_cast<unsigned*>(&p1);
            *reinterpret_cast<uint2*>(smem + feSt + FE_STRIDE) = u;
        }
        {
            __half2 p0 = __lows2half2(f23[0], f23[1]);
            __half2 p1 = __lows2half2(f23[2], f23[3]);
            uint2 u; u.x = *reinterpret_cast<unsigned*>(&p0); u.y = *reinterpret_cast<unsigned*>(&p1);
            *reinterpret_cast<uint2*>(smem + feSt + 2 * FE_STRIDE) = u;
        }
        {
            __half2 p0 = __highs2half2(f23[0], f23[1]);
            __half2 p1 = __highs2half2(f23[2], f23[3]);
            uint2 u; u.x = *reinterpret_cast<unsigned*>(&p0); u.y = *reinterpret_cast<unsigned*>(&p1);
            *reinterpret_cast<uint2*>(smem + feSt + 3 * FE_STRIDE) = u;
        }

        __syncthreads();   // S_B: feats visible; weights(sel) consumed

        if (ti + 2 < NT2) {
            const uint4* srcW = reinterpret_cast<const uint4*>(g_gvfWs) + (size_t)(ti + 2) * 1024;
#pragma unroll
            for (int j = 0; j < 2; j++) {
                int e = j * THREADS + t;
                CPA16(wdA[sel] + wdst(e), srcW + e);
            }
            if (t < 256) {
                int gg = t >> 2, j = t & 3;
                CPA16(idxA[sel] + gg * 80 + j * 16,
                      gidx + (size_t)((ti + 2) * GT + gg) * 16 + j * 4);
            }
            CPCOMMIT();
        }

        // mma over this warp's 2 gvf k-tiles
#pragma unroll
        for (int j = 0; j < 2; j++) {
            uint32_t a0, a1, a2, a3;
            asm volatile("ldmatrix.sync.aligned.m8n8.x4.shared.b16 {%0,%1,%2,%3}, [%4];"
                         : "=r"(a0), "=r"(a1), "=r"(a2), "=r"(a3) : "r"(feLd + j * 32));
#pragma unroll
            for (int nt = 0; nt < NTILES; nt++) {
                asm volatile(
                    "mma.sync.aligned.m16n8k16.row.col.f32.f16.f16.f32 "
                    "{%0,%1,%2,%3}, {%4,%5,%6,%7}, {%8,%9}, {%0,%1,%2,%3};"
                    : "+f"(acc[nt][0]), "+f"(acc[nt][1]), "+f"(acc[nt][2]), "+f"(acc[nt][3])
                    : "r"(a0), "r"(a1), "r"(a2), "r"(a3),
                      "r"(bf[j][nt].x), "r"(bf[j][nt].y));
            }
        }
    }

    // ---- cross-warp K reduction ----
    __syncthreads();
    float* sRed = reinterpret_cast<float*>(smem + RED_OFF);   // [16w][16row][24col]
    {
        const int row0 = lane >> 2, c = lane & 3;
#pragma unroll
        for (int nt = 0; nt < NTILES; nt++) {
            int col = nt * 8 + 2 * c;
            *reinterpret_cast<float2*>(&sRed[(wid * 16 + row0) * 24 + col]) =
                make_float2(acc[nt][0], acc[nt][1]);
            *reinterpret_cast<float2*>(&sRed[(wid * 16 + row0 + 8) * 24 + col]) =
                make_float2(acc[nt][2], acc[nt][3]);
        }
    }
    __syncthreads();

    if (t < BM * A_) {
        int row = t / A_, a = t - row * A_;
        float s = 0.f;
#pragma unroll
        for (int w = 0; w < 16; w++)
            s += sRed[(w * 16 + row) * 24 + a];
        out[(size_t)(bBase + row) * A_ + a] = s;
    }
}

// ================= launch =================
extern "C" void kernel_launch(void* const* d_in, const int* in_sizes, int n_in,
                              void* d_out, int out_size) {
    const float* obs  = (const float*)d_in[0];
    const float* gvfW = (const float*)d_in[1];
    const float* qW   = (const float*)d_in[2];
    const int*   gidx = (const int*)d_in[3];
    float* out = (float*)d_out;

    prep_gvfWs<<<(G_ * 16 + 255) / 256, 256>>>(gvfW);
    prep_qfrag<<<(KT_TOT * NTILES * 32 + 255) / 256, 256>>>(qW);

    cudaFuncSetAttribute(gvf_fused_kernel,
                         cudaFuncAttributeMaxDynamicSharedMemorySize, SMEMA_BYTES);
    gvf_fused_kernel<<<B_ / BM, THREADS, SMEMA_BYTES>>>(obs, gidx, out);
}

// round 13
// speedup vs baseline: 2.2858x; 1.0440x over previous
#include <cuda_runtime.h>
#include <cuda_fp16.h>
#include <cstdint>

// Shapes (fixed)
#define B_      2048
#define OBS_    4096
#define G_      4096
#define A_      18
#define F_      36864

#define BM      16
#define THREADS 512
#define GT      64
#define NT2     64
#define NTILES  3                    // N = 24 (>= 18)
#define KT_TOT  (F_ / 16)            // 2304 global k-tiles

// obs smem: 2 octo-rows (batch rows 0-7, 8-15); per feature f a uint4 =
// {h2(r0,r1),h2(r2,r3),h2(r4,r5),h2(r6,r7)} at byte f*16
#define OCTROWB   65552              // 4096*16 + 16 pad
#define OBS_OFF   0
#define OBS_BYTES (2 * OCTROWB)      // 131104

// 3-deep tile buffers: [wb 16KB][idx 5KB]
#define WB_BYTES   16384
#define IDX_BYTES  (GT * 80)         // 5120
#define BUF_STRIDE (WB_BYTES + IDX_BYTES)   // 21504
#define BUFS_OFF   OBS_BYTES         // 131104
#define SMEM_BYTES (BUFS_OFF + 3 * BUF_STRIDE)   // 195616
#define RED_OFF    BUFS_OFF          // 24576B, aliases buffers post-barrier

// ---- device scratch ----
__device__ uint2 g_gvfWb[(size_t)G_ * 32];                 // gvf weights, mma B-frag order
__device__ uint2 g_qfrag[(size_t)KT_TOT * NTILES * 32];    // qW in mma B-frag order

// ================= helpers =================
__device__ __forceinline__ uint32_t smem_u32(const void* p) {
    return (uint32_t)__cvta_generic_to_shared(p);
}
#define CPA16(dst, src) asm volatile("cp.async.cg.shared.global [%0], [%1], 16;" :: "r"(dst), "l"(src))
#define CPCOMMIT()      asm volatile("cp.async.commit_group;")
#define CPWAIT(n)       asm volatile("cp.async.wait_group %0;" :: "n"(n))

__device__ __forceinline__ uint32_t lds32(uint32_t a) {
    uint32_t v; asm volatile("ld.shared.b32 %0, [%1];" : "=r"(v) : "r"(a)); return v;
}
__device__ __forceinline__ uint2 lds64(uint32_t a) {
    uint2 v; asm volatile("ld.shared.v2.b32 {%0,%1}, [%2];" : "=r"(v.x), "=r"(v.y) : "r"(a)); return v;
}
__device__ __forceinline__ unsigned h2u(float a, float b) {
    __half2 h = __floats2half2_rn(a, b);
    return *reinterpret_cast<unsigned*>(&h);
}

#define MMA_ACC(acc, a0, a1, a2, a3, b0, b1)                                     \
    asm volatile("mma.sync.aligned.m16n8k16.row.col.f32.f16.f16.f32 "            \
                 "{%0,%1,%2,%3}, {%4,%5,%6,%7}, {%8,%9}, {%0,%1,%2,%3};"         \
                 : "+f"(acc[0]), "+f"(acc[1]), "+f"(acc[2]), "+f"(acc[3])        \
                 : "r"(a0), "r"(a1), "r"(a2), "r"(a3), "r"(b0), "r"(b1))

#define MMA_FRESH(d0, d1, d2, d3, a0, a1, a2, a3, b0, b1)                        \
    asm volatile("mma.sync.aligned.m16n8k16.row.col.f32.f16.f16.f32 "            \
                 "{%0,%1,%2,%3}, {%4,%5,%6,%7}, {%8,%9}, {%10,%11,%12,%13};"     \
                 : "=f"(d0), "=f"(d1), "=f"(d2), "=f"(d3)                        \
                 : "r"(a0), "r"(a1), "r"(a2), "r"(a3), "r"(b0), "r"(b1),         \
                   "f"(0.f), "f"(0.f), "f"(0.f), "f"(0.f))

// ================= prep (single launch) =================
// blocks [0, 864): qW -> q B-frags.  blocks [864, 1376): gvfW -> gvf B-frags.
__global__ void prep_all(const float* __restrict__ qW, const float* __restrict__ gvfW) {
    if (blockIdx.x < 864) {
        int e = blockIdx.x * 256 + threadIdx.x;
        if (e >= KT_TOT * NTILES * 32) return;
        int lane = e & 31;
        int nt   = (e >> 5) % NTILES;
        int kt   = e / (32 * NTILES);
        int n  = nt * 8 + (lane >> 2);
        int kb = kt * 16 + 2 * (lane & 3);
        uint2 o;
        float v0 = (n < A_) ? qW[(size_t)n * F_ + kb]     : 0.f;
        float v1 = (n < A_) ? qW[(size_t)n * F_ + kb + 1] : 0.f;
        o.x = h2u(v0, v1);
        v0 = (n < A_) ? qW[(size_t)n * F_ + kb + 8] : 0.f;
        v1 = (n < A_) ? qW[(size_t)n * F_ + kb + 9] : 0.f;
        o.y = h2u(v0, v1);
        g_qfrag[e] = o;
    } else {
        int e = (blockIdx.x - 864) * 256 + threadIdx.x;
        if (e >= G_ * 32) return;
        int g = e >> 5, l = e & 31;
        int gid = l >> 2, tig = l & 3;        // gid = head h, tig -> k pairs
        const float* w = gvfW + (size_t)g * 128 + gid * 16;
        uint2 o;
        o.x = h2u(w[2 * tig],     w[2 * tig + 1]);
        o.y = h2u(w[2 * tig + 8], w[2 * tig + 9]);
        g_gvfWb[e] = o;
    }
}

// ================= fused kernel =================
__global__ __launch_bounds__(THREADS, 1)
void gvf_fused_kernel(const float* __restrict__ obs,
                      const int*   __restrict__ gidx,
                      float* __restrict__ out) {
    extern __shared__ char smem[];
    const int t     = threadIdx.x;
    const int bBase = blockIdx.x * BM;
    const int wid   = t >> 5;
    const int lane  = t & 31;

    uint32_t bufA[3];
#pragma unroll
    for (int s = 0; s < 3; s++) bufA[s] = smem_u32(smem + BUFS_OFF + s * BUF_STRIDE);

    // tile fill: weights (2 CPA16/thread) + idx (t<256)
    auto issue_fill = [&](int ti) {
        if (ti < NT2) {
            const uint4* srcW = reinterpret_cast<const uint4*>(g_gvfWb) + (size_t)ti * 1024;
            uint32_t wb = bufA[ti % 3];
            CPA16(wb + t * 16, srcW + t);
            CPA16(wb + (512 + t) * 16, srcW + 512 + t);
            if (t < 256) {
                int gg = t >> 2, j = t & 3;
                CPA16(wb + WB_BYTES + gg * 80 + j * 16,
                      gidx + (size_t)(ti * GT + gg) * 16 + j * 4);
            }
        }
        CPCOMMIT();
    };

    issue_fill(0);
    issue_fill(1);

    // ---- phase 0: obs -> octo smem ----
    for (int e = t; e < 2 * (OBS_ / 4); e += THREADS) {
        int o = e >> 10, fg = e & 1023, f = fg * 4;
        const float* bp = obs + (size_t)(bBase + o * 8) * OBS_ + f;
        float4 rv[8];
#pragma unroll
        for (int i = 0; i < 8; i++)
            rv[i] = *reinterpret_cast<const float4*>(bp + (size_t)i * OBS_);
        const float* rr = reinterpret_cast<const float*>(rv);
        char* dst = smem + OBS_OFF + o * OCTROWB + f * 16;
#pragma unroll
        for (int j = 0; j < 4; j++) {
            uint4 u;
            u.x = h2u(rr[0  + j], rr[4  + j]);
            u.y = h2u(rr[8  + j], rr[12 + j]);
            u.z = h2u(rr[16 + j], rr[20 + j]);
            u.w = h2u(rr[24 + j], rr[28 + j]);
            *reinterpret_cast<uint4*>(dst + j * 16) = u;
        }
    }
    __syncthreads();   // obs ready

    const int gid = lane >> 2, tig = lane & 3;
    const uint32_t wordoff = (uint32_t)(gid >> 1) * 4;
    const uint32_t psel = (gid & 1) ? 0x7632u : 0x5410u;
    const uint32_t O0 = smem_u32(smem + OBS_OFF) + wordoff;
    const uint32_t O1 = O0 + OCTROWB;

    float acc[NTILES][4];
#pragma unroll
    for (int nt = 0; nt < NTILES; nt++)
#pragma unroll
        for (int r = 0; r < 4; r++) acc[nt][r] = 0.f;

    // ---- obs-part q GEMM (16 k-tiles per warp, from octo smem) ----
    for (int j = 0; j < 16; j++) {
        const int gkt = wid * 16 + j;
        const uint32_t cb = (uint32_t)(gkt * 16 + 2 * tig) * 16;
        uint2 bf[NTILES];
#pragma unroll
        for (int nt = 0; nt < NTILES; nt++)
            bf[nt] = __ldg(&g_qfrag[((size_t)gkt * NTILES + nt) * 32 + lane]);
        uint32_t l00 = lds32(O0 + cb),       l01 = lds32(O0 + cb + 16);
        uint32_t l10 = lds32(O1 + cb),       l11 = lds32(O1 + cb + 16);
        uint32_t l02 = lds32(O0 + cb + 128), l03 = lds32(O0 + cb + 144);
        uint32_t l12 = lds32(O1 + cb + 128), l13 = lds32(O1 + cb + 144);
        uint32_t a0 = __byte_perm(l00, l01, psel);
        uint32_t a1 = __byte_perm(l10, l11, psel);
        uint32_t a2 = __byte_perm(l02, l03, psel);
        uint32_t a3 = __byte_perm(l12, l13, psel);
#pragma unroll
        for (int nt = 0; nt < NTILES; nt++)
            MMA_ACC(acc[nt], a0, a1, a2, a3, bf[nt].x, bf[nt].y);
    }

    // ---- gvf tiles: gather -> gvf-mma -> (register relu) -> q-mma ----
    for (int ti = 0; ti < NT2; ti++) {
        CPWAIT(1);
        __syncthreads();            // buffers (ti) visible; (ti+2)%3 free
        issue_fill(ti + 2);

        const uint32_t wbB  = bufA[ti % 3];
        const uint32_t idxB = wbB + WB_BYTES;

#pragma unroll
        for (int j = 0; j < 2; j++) {                 // warp's 2 k-tiles
            uint32_t qa[4];
#pragma unroll
            for (int p = 0; p < 2; p++) {             // even / odd gvf
                int gg = wid * 4 + 2 * j + p;         // local gvf
                uint32_t ib = idxB + gg * 80 + 2 * tig * 4;
                uint2 iA = lds64(ib);                 // idx[2tig], idx[2tig+1]
                uint2 iB = lds64(ib + 32);            // idx[2tig+8], idx[2tig+9]
                uint32_t l00 = lds32(O0 + iA.x * 16), l01 = lds32(O0 + iA.y * 16);
                uint32_t l10 = lds32(O1 + iA.x * 16), l11 = lds32(O1 + iA.y * 16);
                uint32_t l02 = lds32(O0 + iB.x * 16), l03 = lds32(O0 + iB.y * 16);
                uint32_t l12 = lds32(O1 + iB.x * 16), l13 = lds32(O1 + iB.y * 16);
                uint32_t a0 = __byte_perm(l00, l01, psel);
                uint32_t a1 = __byte_perm(l10, l11, psel);
                uint32_t a2 = __byte_perm(l02, l03, psel);
                uint32_t a3 = __byte_perm(l12, l13, psel);
                uint2 wb = lds64(wbB + gg * 256 + lane * 8);
                float d0, d1, d2, d3;
                MMA_FRESH(d0, d1, d2, d3, a0, a1, a2, a3, wb.x, wb.y);
                // relu + pack: D-frag -> q A-frag halves
                qa[2 * p]     = h2u(fmaxf(d0, 0.f), fmaxf(d1, 0.f));  // rows gid
                qa[2 * p + 1] = h2u(fmaxf(d2, 0.f), fmaxf(d3, 0.f));  // rows gid+8
            }
            const int gkt = 256 + ti * 32 + 2 * wid + j;
#pragma unroll
            for (int nt = 0; nt < NTILES; nt++) {
                uint2 bf = __ldg(&g_qfrag[((size_t)gkt * NTILES + nt) * 32 + lane]);
                MMA_ACC(acc[nt], qa[0], qa[1], qa[2], qa[3], bf.x, bf.y);
            }
        }
    }

    // ---- cross-warp K reduction ----
    __syncthreads();
    float* sRed = reinterpret_cast<float*>(smem + RED_OFF);   // [16w][16row][24col]
    {
#pragma unroll
        for (int nt = 0; nt < NTILES; nt++) {
            int col = nt * 8 + 2 * tig;
            *reinterpret_cast<float2*>(&sRed[(wid * 16 + gid) * 24 + col]) =
                make_float2(acc[nt][0], acc[nt][1]);
            *reinterpret_cast<float2*>(&sRed[(wid * 16 + gid + 8) * 24 + col]) =
                make_float2(acc[nt][2], acc[nt][3]);
        }
    }
    __syncthreads();

    if (t < BM * A_) {
        int row = t / A_, a = t - row * A_;
        float s = 0.f;
#pragma unroll
        for (int w = 0; w < 16; w++)
            s += sRed[(w * 16 + row) * 24 + a];
        out[(size_t)(bBase + row) * A_ + a] = s;
    }
}

// ================= launch =================
extern "C" void kernel_launch(void* const* d_in, const int* in_sizes, int n_in,
                              void* d_out, int out_size) {
    const float* obs  = (const float*)d_in[0];
    const float* gvfW = (const float*)d_in[1];
    const float* qW   = (const float*)d_in[2];
    const int*   gidx = (const int*)d_in[3];
    float* out = (float*)d_out;

    prep_all<<<864 + 512, 256>>>(qW, gvfW);

    cudaFuncSetAttribute(gvf_fused_kernel,
                         cudaFuncAttributeMaxDynamicSharedMemorySize, SMEM_BYTES);
    gvf_fused_kernel<<<B_ / BM, THREADS, SMEM_BYTES>>>(obs, gidx, out);
}

// round 15
// speedup vs baseline: 2.3067x; 1.0092x over previous
#include <cuda_runtime.h>
#include <cuda_fp16.h>
#include <cstdint>

// Shapes (fixed)
#define B_      2048
#define OBS_    4096
#define G_      4096
#define A_      18
#define F_      36864

#define BM      16
#define THREADS 512
#define GT      64
#define NT2     64
#define NTILES  3                    // N = 24 (>= 18)
#define KT_TOT  (F_ / 16)            // 2304 global k-tiles

// obs smem: 2 octo-rows (batch rows 0-7, 8-15); per feature f a uint4 =
// {h2(r0,r1),h2(r2,r3),h2(r4,r5),h2(r6,r7)} at byte f*16
#define OCTROWB   65552              // 4096*16 + 16 pad
#define OBS_OFF   0
#define OBS_BYTES (2 * OCTROWB)      // 131104

// 3-deep tile buffers: [wb 16KB][idx 5KB]
#define WB_BYTES   16384
#define IDX_BYTES  (GT * 80)         // 5120
#define BUF_STRIDE (WB_BYTES + IDX_BYTES)   // 21504
#define BUFS_OFF   OBS_BYTES         // 131104
#define SMEM_BYTES (BUFS_OFF + 3 * BUF_STRIDE)   // 195616
#define RED_OFF    BUFS_OFF          // 24576B, aliases buffers post-barrier

// ---- device scratch ----
__device__ uint2 g_gvfWb[(size_t)G_ * 32];                 // gvf weights, mma B-frag order
__device__ uint2 g_qfrag[(size_t)KT_TOT * NTILES * 32];    // qW in mma B-frag order
__device__ int   g_idxs[(size_t)G_ * 16];                  // gidx * 16 (byte offsets)

// ================= helpers =================
__device__ __forceinline__ uint32_t smem_u32(const void* p) {
    return (uint32_t)__cvta_generic_to_shared(p);
}
#define CPA16(dst, src) asm volatile("cp.async.cg.shared.global [%0], [%1], 16;" :: "r"(dst), "l"(src))
#define CPCOMMIT()      asm volatile("cp.async.commit_group;")
#define CPWAIT(n)       asm volatile("cp.async.wait_group %0;" :: "n"(n))

__device__ __forceinline__ uint32_t lds32(uint32_t a) {
    uint32_t v; asm volatile("ld.shared.b32 %0, [%1];" : "=r"(v) : "r"(a)); return v;
}
__device__ __forceinline__ uint2 lds64(uint32_t a) {
    uint2 v; asm volatile("ld.shared.v2.b32 {%0,%1}, [%2];" : "=r"(v.x), "=r"(v.y) : "r"(a)); return v;
}
__device__ __forceinline__ unsigned h2u(float a, float b) {
    __half2 h = __floats2half2_rn(a, b);
    return *reinterpret_cast<unsigned*>(&h);
}

#define MMA_ACC(acc, a0, a1, a2, a3, b0, b1)                                     \
    asm volatile("mma.sync.aligned.m16n8k16.row.col.f32.f16.f16.f32 "            \
                 "{%0,%1,%2,%3}, {%4,%5,%6,%7}, {%8,%9}, {%0,%1,%2,%3};"         \
                 : "+f"(acc[0]), "+f"(acc[1]), "+f"(acc[2]), "+f"(acc[3])        \
                 : "r"(a0), "r"(a1), "r"(a2), "r"(a3), "r"(b0), "r"(b1))

#define MMA_FRESH(d0, d1, d2, d3, a0, a1, a2, a3, b0, b1)                        \
    asm volatile("mma.sync.aligned.m16n8k16.row.col.f32.f16.f16.f32 "            \
                 "{%0,%1,%2,%3}, {%4,%5,%6,%7}, {%8,%9}, {%10,%11,%12,%13};"     \
                 : "=f"(d0), "=f"(d1), "=f"(d2), "=f"(d3)                        \
                 : "r"(a0), "r"(a1), "r"(a2), "r"(a3), "r"(b0), "r"(b1),         \
                   "f"(0.f), "f"(0.f), "f"(0.f), "f"(0.f))

// ================= prep (single launch) =================
// blocks [0,864): qW -> q B-frags. [864,1376): gvfW -> gvf B-frags. [1376,1632): idx*16.
__global__ void prep_all(const float* __restrict__ qW,
                         const float* __restrict__ gvfW,
                         const int*   __restrict__ gidx) {
    if (blockIdx.x < 864) {
        int e = blockIdx.x * 256 + threadIdx.x;
        if (e >= KT_TOT * NTILES * 32) return;
        int lane = e & 31;
        int nt   = (e >> 5) % NTILES;
        int kt   = e / (32 * NTILES);
        int n  = nt * 8 + (lane >> 2);
        int kb = kt * 16 + 2 * (lane & 3);
        uint2 o;
        float v0 = (n < A_) ? qW[(size_t)n * F_ + kb]     : 0.f;
        float v1 = (n < A_) ? qW[(size_t)n * F_ + kb + 1] : 0.f;
        o.x = h2u(v0, v1);
        v0 = (n < A_) ? qW[(size_t)n * F_ + kb + 8] : 0.f;
        v1 = (n < A_) ? qW[(size_t)n * F_ + kb + 9] : 0.f;
        o.y = h2u(v0, v1);
        g_qfrag[e] = o;
    } else if (blockIdx.x < 1376) {
        int e = (blockIdx.x - 864) * 256 + threadIdx.x;
        if (e >= G_ * 32) return;
        int g = e >> 5, l = e & 31;
        int gid = l >> 2, tig = l & 3;
        const float* w = gvfW + (size_t)g * 128 + gid * 16;
        uint2 o;
        o.x = h2u(w[2 * tig],     w[2 * tig + 1]);
        o.y = h2u(w[2 * tig + 8], w[2 * tig + 9]);
        g_gvfWb[e] = o;
    } else {
        int e = (blockIdx.x - 1376) * 256 + threadIdx.x;
        if (e < G_ * 16) g_idxs[e] = gidx[e] * 16;
    }
}

// ================= fused kernel =================
__global__ __launch_bounds__(THREADS, 1)
void gvf_fused_kernel(const float* __restrict__ obs,
                      float* __restrict__ out) {
    extern __shared__ char smem[];
    const int t     = threadIdx.x;
    const int bBase = blockIdx.x * BM;
    const int wid   = t >> 5;
    const int lane  = t & 31;

    uint32_t bufA[3];
#pragma unroll
    for (int s = 0; s < 3; s++) bufA[s] = smem_u32(smem + BUFS_OFF + s * BUF_STRIDE);

    // tile fill: weights (2 CPA16/thread) + prescaled idx (t<256)
    auto issue_fill = [&](int ti) {
        if (ti < NT2) {
            const uint4* srcW = reinterpret_cast<const uint4*>(g_gvfWb) + (size_t)ti * 1024;
            uint32_t wb = bufA[ti % 3];
            CPA16(wb + t * 16, srcW + t);
            CPA16(wb + (512 + t) * 16, srcW + 512 + t);
            if (t < 256) {
                int gg = t >> 2, j = t & 3;
                CPA16(wb + WB_BYTES + gg * 80 + j * 16,
                      g_idxs + (size_t)(ti * GT + gg) * 16 + j * 4);
            }
        }
        CPCOMMIT();
    };

    issue_fill(0);
    issue_fill(1);

    // ---- phase 0: obs -> octo smem ----
    for (int e = t; e < 2 * (OBS_ / 4); e += THREADS) {
        int o = e >> 10, fg = e & 1023, f = fg * 4;
        const float* bp = obs + (size_t)(bBase + o * 8) * OBS_ + f;
        float4 rv[8];
#pragma unroll
        for (int i = 0; i < 8; i++)
            rv[i] = *reinterpret_cast<const float4*>(bp + (size_t)i * OBS_);
        const float* rr = reinterpret_cast<const float*>(rv);
        char* dst = smem + OBS_OFF + o * OCTROWB + f * 16;
#pragma unroll
        for (int j = 0; j < 4; j++) {
            uint4 u;
            u.x = h2u(rr[0  + j], rr[4  + j]);
            u.y = h2u(rr[8  + j], rr[12 + j]);
            u.z = h2u(rr[16 + j], rr[20 + j]);
            u.w = h2u(rr[24 + j], rr[28 + j]);
            *reinterpret_cast<uint4*>(dst + j * 16) = u;
        }
    }
    __syncthreads();   // obs ready

    const int gid = lane >> 2, tig = lane & 3;
    const uint32_t wordoff = (uint32_t)(gid >> 1) * 4;
    const uint32_t psel = (gid & 1) ? 0x7632u : 0x5410u;
    const uint32_t O0 = smem_u32(smem + OBS_OFF) + wordoff;
    const uint32_t O1 = O0 + OCTROWB;

    float acc[NTILES][4];
#pragma unroll
    for (int nt = 0; nt < NTILES; nt++)
#pragma unroll
        for (int r = 0; r < 4; r++) acc[nt][r] = 0.f;

    // ---- obs-part q GEMM (16 k-tiles per warp, from octo smem) ----
    for (int j = 0; j < 16; j++) {
        const int gkt = wid * 16 + j;
        const uint32_t cb = (uint32_t)(gkt * 16 + 2 * tig) * 16;
        uint2 bf[NTILES];
#pragma unroll
        for (int nt = 0; nt < NTILES; nt++)
            bf[nt] = __ldg(&g_qfrag[((size_t)gkt * NTILES + nt) * 32 + lane]);
        uint32_t l00 = lds32(O0 + cb),       l01 = lds32(O0 + cb + 16);
        uint32_t l10 = lds32(O1 + cb),       l11 = lds32(O1 + cb + 16);
        uint32_t l02 = lds32(O0 + cb + 128), l03 = lds32(O0 + cb + 144);
        uint32_t l12 = lds32(O1 + cb + 128), l13 = lds32(O1 + cb + 144);
        uint32_t a0 = __byte_perm(l00, l01, psel);
        uint32_t a1 = __byte_perm(l10, l11, psel);
        uint32_t a2 = __byte_perm(l02, l03, psel);
        uint32_t a3 = __byte_perm(l12, l13, psel);
#pragma unroll
        for (int nt = 0; nt < NTILES; nt++)
            MMA_ACC(acc[nt], a0, a1, a2, a3, bf[nt].x, bf[nt].y);
    }

    // ---- gvf tiles: hoisted scalars, 16-deep gather batches ----
    for (int ti = 0; ti < NT2; ti++) {
        CPWAIT(1);
        __syncthreads();            // buffers (ti) visible; (ti+2)%3 free
        issue_fill(ti + 2);

        const uint32_t wbB  = bufA[ti % 3];
        const uint32_t idxB = wbB + WB_BYTES;

        // hoist: idx pairs + weight frags for the warp's 4 gvfs
        uint2 iA[4], iB[4], wv[4];
#pragma unroll
        for (int g = 0; g < 4; g++) {
            const int gg = wid * 4 + g;
            uint32_t ib = idxB + gg * 80 + tig * 8;
            iA[g] = lds64(ib);
            iB[g] = lds64(ib + 32);
            wv[g] = lds64(wbB + gg * 256 + lane * 8);
        }
        // hoist: q B-frags for both k-tiles (global, long latency — hidden)
        uint2 bf[2][NTILES];
        {
            const int gkt0 = 256 + ti * 32 + 2 * wid;
#pragma unroll
            for (int j = 0; j < 2; j++)
#pragma unroll
                for (int nt = 0; nt < NTILES; nt++)
                    bf[j][nt] = __ldg(&g_qfrag[((size_t)(gkt0 + j) * NTILES + nt) * 32 + lane]);
        }

#pragma unroll
        for (int j = 0; j < 2; j++) {
            // batch all 16 gather loads for this j-group (2 gvfs)
            uint32_t L[2][8];
#pragma unroll
            for (int p = 0; p < 2; p++) {
                const int g = 2 * j + p;
                L[p][0] = lds32(O0 + iA[g].x);  L[p][1] = lds32(O0 + iA[g].y);
                L[p][2] = lds32(O1 + iA[g].x);  L[p][3] = lds32(O1 + iA[g].y);
                L[p][4] = lds32(O0 + iB[g].x);  L[p][5] = lds32(O0 + iB[g].y);
                L[p][6] = lds32(O1 + iB[g].x);  L[p][7] = lds32(O1 + iB[g].y);
            }
            uint32_t qa[4];
#pragma unroll
            for (int p = 0; p < 2; p++) {
                const int g = 2 * j + p;
                uint32_t a0 = __byte_perm(L[p][0], L[p][1], psel);
                uint32_t a1 = __byte_perm(L[p][2], L[p][3], psel);
                uint32_t a2 = __byte_perm(L[p][4], L[p][5], psel);
                uint32_t a3 = __byte_perm(L[p][6], L[p][7], psel);
                float d0, d1, d2, d3;
                MMA_FRESH(d0, d1, d2, d3, a0, a1, a2, a3, wv[g].x, wv[g].y);
                qa[2 * p]     = h2u(fmaxf(d0, 0.f), fmaxf(d1, 0.f));
                qa[2 * p + 1] = h2u(fmaxf(d2, 0.f), fmaxf(d3, 0.f));
            }
#pragma unroll
            for (int nt = 0; nt < NTILES; nt++)
                MMA_ACC(acc[nt], qa[0], qa[1], qa[2], qa[3], bf[j][nt].x, bf[j][nt].y);
        }
    }

    // ---- cross-warp K reduction ----
    __syncthreads();
    float* sRed = reinterpret_cast<float*>(smem + RED_OFF);   // [16w][16row][24col]
    {
#pragma unroll
        for (int nt = 0; nt < NTILES; nt++) {
            int col = nt * 8 + 2 * tig;
            *reinterpret_cast<float2*>(&sRed[(wid * 16 + gid) * 24 + col]) =
                make_float2(acc[nt][0], acc[nt][1]);
            *reinterpret_cast<float2*>(&sRed[(wid * 16 + gid + 8) * 24 + col]) =
                make_float2(acc[nt][2], acc[nt][3]);
        }
    }
    __syncthreads();

    if (t < BM * A_) {
        int row = t / A_, a = t - row * A_;
        float s = 0.f;
#pragma unroll
        for (int w = 0; w < 16; w++)
            s += sRed[(w * 16 + row) * 24 + a];
        out[(size_t)(bBase + row) * A_ + a] = s;
    }
}

// ================= launch =================
extern "C" void kernel_launch(void* const* d_in, const int* in_sizes, int n_in,
                              void* d_out, int out_size) {
    const float* obs  = (const float*)d_in[0];
    const float* gvfW = (const float*)d_in[1];
    const float* qW   = (const float*)d_in[2];
    const int*   gidx = (const int*)d_in[3];
    float* out = (float*)d_out;

    prep_all<<<864 + 512 + 256, 256>>>(qW, gvfW, gidx);

    cudaFuncSetAttribute(gvf_fused_kernel,
                         cudaFuncAttributeMaxDynamicSharedMemorySize, SMEM_BYTES);
    gvf_fused_kernel<<<B_ / BM, THREADS, SMEM_BYTES>>>(obs, out);
}